// round 13
// baseline (speedup 1.0000x reference)
#include <cuda_runtime.h>
#include <cuda_bf16.h>
#include <math.h>
#include <stdint.h>

// ---------------------------------------------------------------------------
// Problem constants
// ---------------------------------------------------------------------------
#define BATCH 4
#define LIN   40960
#define CCH   512
#define T0    8192
#define T1    2048
#define T2    1024
#define T3    512
#define TN    256
#define DMLP  2048

// ---------------------------------------------------------------------------
// Scratch (device globals; no allocation allowed)
// ---------------------------------------------------------------------------
__device__ __nv_bfloat16 g_h0h[BATCH * T0 * CCH], g_h0l[BATCH * T0 * CCH];
__device__ __nv_bfloat16 g_h1h[BATCH * T1 * CCH], g_h1l[BATCH * T1 * CCH];
__device__ __nv_bfloat16 g_h2h[BATCH * T2 * CCH], g_h2l[BATCH * T2 * CCH];
__device__ __nv_bfloat16 g_fh [BATCH * T3 * CCH], g_fl [BATCH * T3 * CCH];
__device__ __nv_bfloat16 g_z1h[BATCH * T3 * DMLP], g_z1l[BATCH * T3 * DMLP];
__device__ float g_f  [BATCH * T3 * CCH];
__device__ float g_z2 [BATCH * T3 * DMLP];
__device__ float g_raw[BATCH * T1 * CCH];
__device__ float g_imp[BATCH * T3];
__device__ float g_cs [BATCH * T3];
__device__ __nv_bfloat16 g_w1h[8 * CCH * CCH], g_w1l[8 * CCH * CCH];
__device__ __nv_bfloat16 g_w2h[4 * CCH * CCH], g_w2l[4 * CCH * CCH];
__device__ __nv_bfloat16 g_w3h[4 * CCH * CCH], g_w3l[4 * CCH * CCH];
__device__ __nv_bfloat16 g_mw1h[CCH * DMLP],   g_mw1l[CCH * DMLP];
__device__ __nv_bfloat16 g_mw2h[DMLP * DMLP],  g_mw2l[DMLP * DMLP];
__device__ float g_w0f[10 * CCH];

// ---------------------------------------------------------------------------
// Helpers
// ---------------------------------------------------------------------------
__device__ __forceinline__ int refl(int p, int n) {
    return p < 0 ? -p : (p >= n ? 2 * n - 2 - p : p);
}

__device__ __forceinline__ float gelu_exact(float v) {
    return 0.5f * v * (1.f + erff(v * 0.70710678118654752f));
}

__device__ __forceinline__ void fsplit(float v, __nv_bfloat16& h, __nv_bfloat16& l) {
    h = __float2bfloat16(v);
    l = __float2bfloat16(v - __bfloat162float(h));
}

__device__ __forceinline__ void ldsm_x4(unsigned addr, unsigned* r) {
    asm volatile("ldmatrix.sync.aligned.m8n8.x4.shared.b16 {%0,%1,%2,%3}, [%4];"
                 : "=r"(r[0]), "=r"(r[1]), "=r"(r[2]), "=r"(r[3]) : "r"(addr));
}
__device__ __forceinline__ void ldsm_x2t(unsigned addr, unsigned* r) {
    asm volatile("ldmatrix.sync.aligned.m8n8.x2.trans.shared.b16 {%0,%1}, [%2];"
                 : "=r"(r[0]), "=r"(r[1]) : "r"(addr));
}
__device__ __forceinline__ void mma16816(float* d, const unsigned* a, const unsigned* b) {
    asm volatile(
        "mma.sync.aligned.m16n8k16.row.col.f32.bf16.bf16.f32 "
        "{%0,%1,%2,%3},{%4,%5,%6,%7},{%8,%9},{%0,%1,%2,%3};"
        : "+f"(d[0]), "+f"(d[1]), "+f"(d[2]), "+f"(d[3])
        : "r"(a[0]), "r"(a[1]), "r"(a[2]), "r"(a[3]), "r"(b[0]), "r"(b[1]));
}

// Block-wide (sum, sumsq) reduction. sred >= 64 floats.
__device__ __forceinline__ float2 block_reduce2(float v1, float v2, float* sred) {
    __syncthreads();
    int lane = threadIdx.x & 31, wid = threadIdx.x >> 5;
    int nw = blockDim.x >> 5;
#pragma unroll
    for (int o = 16; o > 0; o >>= 1) {
        v1 += __shfl_down_sync(0xffffffffu, v1, o);
        v2 += __shfl_down_sync(0xffffffffu, v2, o);
    }
    if (lane == 0) { sred[wid] = v1; sred[wid + 32] = v2; }
    __syncthreads();
    if (wid == 0) {
        v1 = (lane < nw) ? sred[lane] : 0.f;
        v2 = (lane < nw) ? sred[lane + 32] : 0.f;
#pragma unroll
        for (int o = 16; o > 0; o >>= 1) {
            v1 += __shfl_down_sync(0xffffffffu, v1, o);
            v2 += __shfl_down_sync(0xffffffffu, v2, o);
        }
        if (lane == 0) { sred[0] = v1; sred[32] = v2; }
    }
    __syncthreads();
    return make_float2(sred[0], sred[32]);
}

// ---------------------------------------------------------------------------
// Weight prep
// ---------------------------------------------------------------------------
// conv weights w[c][ci][tap] -> split bf16 at [(tap*CI+ci)][c]  (K tap-major)
__global__ void k_wsplit_conv(const float* __restrict__ w,
                              __nv_bfloat16* __restrict__ wh,
                              __nv_bfloat16* __restrict__ wl,
                              int CI, int KW, int total) {
    int idx = blockIdx.x * blockDim.x + threadIdx.x;
    if (idx >= total) return;
    int ck = CI * KW;
    int c = idx / ck, rem = idx - c * ck;
    int ci = rem / KW, tap = rem - ci * KW;
    __nv_bfloat16 h, l;
    fsplit(w[idx], h, l);
    int o = (tap * CI + ci) * CCH + c;
    wh[o] = h; wl[o] = l;
}

// plain elementwise split (row-major [K][N] kept)
__global__ void k_split(const float* __restrict__ src,
                        __nv_bfloat16* __restrict__ h,
                        __nv_bfloat16* __restrict__ l, int total) {
    int idx = blockIdx.x * blockDim.x + threadIdx.x;
    if (idx >= total) return;
    __nv_bfloat16 hh, ll;
    fsplit(src[idx], hh, ll);
    h[idx] = hh; l[idx] = ll;
}

// conv0 weight transpose w[c][0][k] -> w0f[k*512+c]
__global__ void k_w0trans(const float* __restrict__ w, float* __restrict__ wt) {
    int idx = blockIdx.x * blockDim.x + threadIdx.x;
    if (idx < 10 * CCH) {
        int c = idx / 10, k = idx - c * 10;
        wt[k * CCH + c] = w[idx];
    }
}

// ---------------------------------------------------------------------------
// conv0 (1->512, k=10, s=5, reflect pad 3) + ChannelNorm + ReLU -> bf16 split
// ---------------------------------------------------------------------------
__global__ __launch_bounds__(512) void k_conv0(
    const float* __restrict__ x, const float* __restrict__ w0t,
    const float* __restrict__ bias, const float* __restrict__ nw,
    const float* __restrict__ nb,
    __nv_bfloat16* __restrict__ oh, __nv_bfloat16* __restrict__ ol) {
    const int TT = 8, KW = 10, S = 5, PAD = 3;
    const int W = S * (TT - 1) + KW;  // 45
    __shared__ float sx[48];
    __shared__ float sred[64];
    int b = blockIdx.y, t0 = blockIdx.x * TT, c = threadIdx.x;
    if (c < W) {
        int p = refl(S * t0 - PAD + c, LIN);
        sx[c] = x[b * LIN + p];
    }
    __syncthreads();
    float acc[TT];
    float bi = bias[c];
#pragma unroll
    for (int tt = 0; tt < TT; tt++) acc[tt] = bi;
#pragma unroll
    for (int k = 0; k < KW; k++) {
        float w = w0t[k * CCH + c];
#pragma unroll
        for (int tt = 0; tt < TT; tt++) acc[tt] = fmaf(w, sx[S * tt + k], acc[tt]);
    }
    float gw = nw[c], gb = nb[c];
    for (int tt = 0; tt < TT; tt++) {
        float2 s = block_reduce2(acc[tt], acc[tt] * acc[tt], sred);
        float mean = s.x * (1.f / 512.f);
        float var  = (s.y - s.x * s.x * (1.f / 512.f)) * (1.f / 511.f);
        float inv  = rsqrtf(var + 1e-5f);
        float v    = fmaxf((acc[tt] - mean) * inv * gw + gb, 0.f);
        __nv_bfloat16 h, l;
        fsplit(v, h, l);
        size_t o = ((size_t)(b * T0 + t0 + tt)) * CCH + c;
        oh[o] = h; ol[o] = l;
    }
}

// ---------------------------------------------------------------------------
// Tensor-core split-bf16 GEMM with implicit im2col A-loader.
//   C[M,N] = A[M,K] * B[K,N];  A row t, k=(tap*512+ci) -> in[b][S*t-PAD+tap][ci]
//   (KW==1 -> plain GEMM)
// 3-pass: AhBh + AhBl + AlBh into fp32 acc.
// BM=128, BN=128, KT=32. 256 threads, 8 warps (2x4), warp tile 64x32.
// Double-buffered smem + register prefetch, ONE __syncthreads per tile:
//   iter kt: sync; STS tile kt+1 -> buf (kt+1)&1; LDG tile kt+2 -> regs;
//            compute tile kt from buf kt&1.
// Stage layout (bytes): Ah 10240 | Al 10240 | Bh 8704 | Bl 8704 = 37888; x2 stages.
// EPI: 0 raw fp32 -> outF;  1 bias+gelu fp32 -> outF;  2 bias+gelu -> split hi/lo
// ---------------------------------------------------------------------------
#define ASTR 40   // A smem row stride in bf16 (80B rows: conflict-free ldmatrix)
#define BSTR 136  // B smem row stride in bf16 (272B rows: conflict-free)
#define STGB 37888u
#define SMEM_TOT (2 * 37888)

#define TG_LOAD(KT_IDX)                                                      \
    {                                                                        \
        int kk0 = (KT_IDX) * 32;                                             \
        int tap = (KW == 1) ? 0 : (kk0 >> 9);                                \
        int ci0 = (KW == 1) ? kk0 : (kk0 & 511);                             \
        for (int i = 0; i < 2; i++) {                                        \
            int tt = t0m + am[i];                                            \
            int r = (KW == 1) ? tt : refl(S * tt - PAD + tap, TIN);          \
            size_t offA = (size_t)(bb * TIN + r) * astride + ci0 + akk;      \
            pah[i] = *(const uint4*)(AHi + offA);                            \
            pal[i] = *(const uint4*)(ALo + offA);                            \
            size_t offB = (size_t)(kk0 + bk[i]) * N + n0 + bnn;              \
            pbh[i] = *(const uint4*)(BHi + offB);                            \
            pbl[i] = *(const uint4*)(BLo + offB);                            \
        }                                                                    \
    }

#define TG_STORE(ST)                                                         \
    {                                                                        \
        unsigned stb_ = (unsigned)(ST) * STGB;                               \
        for (int i = 0; i < 2; i++) {                                        \
            *(uint4*)(dsm + stb_ + (unsigned)((am[i] * ASTR + akk) * 2))           = pah[i]; \
            *(uint4*)(dsm + stb_ + 10240u + (unsigned)((am[i] * ASTR + akk) * 2))  = pal[i]; \
            *(uint4*)(dsm + stb_ + 20480u + (unsigned)((bk[i] * BSTR + bnn) * 2))  = pbh[i]; \
            *(uint4*)(dsm + stb_ + 29184u + (unsigned)((bk[i] * BSTR + bnn) * 2))  = pbl[i]; \
        }                                                                    \
    }

template <int KW, int S, int PAD, int EPI>
__global__ __launch_bounds__(256, 1) void k_tgemm(
    const __nv_bfloat16* __restrict__ AHi, const __nv_bfloat16* __restrict__ ALo,
    const __nv_bfloat16* __restrict__ BHi, const __nv_bfloat16* __restrict__ BLo,
    const float* __restrict__ bias, float* __restrict__ outF,
    __nv_bfloat16* __restrict__ outHi, __nv_bfloat16* __restrict__ outLo,
    int TIN, int TOUT, int N, int K, int astride) {
    extern __shared__ __align__(16) unsigned char dsm[];
    const int tid = threadIdx.x;
    const int n0 = blockIdx.x * 128;
    const int t0m = blockIdx.y * 128;
    const int bb = blockIdx.z;

    const unsigned base0 = (unsigned)__cvta_generic_to_shared(dsm);
    const unsigned baseAh = base0;
    const unsigned baseAl = base0 + 10240;
    const unsigned baseBh = base0 + 20480;
    const unsigned baseBl = base0 + 29184;

    float acc[4][4][4];
#pragma unroll
    for (int mi = 0; mi < 4; mi++)
#pragma unroll
        for (int ni = 0; ni < 4; ni++)
#pragma unroll
            for (int q = 0; q < 4; q++) acc[mi][ni][q] = 0.f;

    uint4 pah[2], pal[2], pbh[2], pbl[2];
    const int am[2] = { (tid >> 2), (tid >> 2) + 64 };
    const int akk = (tid & 3) * 8;
    const int bk[2] = { (tid >> 4), (tid >> 4) + 16 };
    const int bnn = (tid & 15) * 8;

    const int warp = tid >> 5, lane = tid & 31;
    const int wm = warp >> 2, wn = warp & 3;
    const int lrow = lane & 15, lko = (lane >> 4) * 8;

    const int NKT = K / 32;
    // prologue: tile0 -> buf0 (no barrier needed before first STS), tile1 -> regs
    TG_LOAD(0)
    TG_STORE(0)
    TG_LOAD(1)
    for (int kt = 0; kt < NKT; kt++) {
        __syncthreads();  // single barrier per tile (see header comment)
        if (kt + 1 < NKT) {
            TG_STORE((kt + 1) & 1)
            if (kt + 2 < NKT) TG_LOAD(kt + 2)
        }
        const unsigned stb = (unsigned)(kt & 1) * STGB;
#pragma unroll
        for (int ks = 0; ks < 2; ks++) {
            unsigned ah[4][4], al[4][4], bh[4][2], bl[4][2];
#pragma unroll
            for (int mi = 0; mi < 4; mi++) {
                int row = wm * 64 + mi * 16 + lrow;
                unsigned offA = stb + (unsigned)((row * ASTR + ks * 16 + lko) * 2);
                ldsm_x4(baseAh + offA, ah[mi]);
                ldsm_x4(baseAl + offA, al[mi]);
            }
#pragma unroll
            for (int ni = 0; ni < 4; ni++) {
                int rb = ks * 16 + lrow;
                unsigned offB = stb + (unsigned)((rb * BSTR + wn * 32 + ni * 8) * 2);
                ldsm_x2t(baseBh + offB, bh[ni]);
                ldsm_x2t(baseBl + offB, bl[ni]);
            }
#pragma unroll
            for (int mi = 0; mi < 4; mi++)
#pragma unroll
                for (int ni = 0; ni < 4; ni++) {
                    mma16816(acc[mi][ni], ah[mi], bh[ni]);
                    mma16816(acc[mi][ni], ah[mi], bl[ni]);
                    mma16816(acc[mi][ni], al[mi], bh[ni]);
                }
        }
    }

    // epilogue
    int g = lane >> 2, tig = lane & 3;
#pragma unroll
    for (int mi = 0; mi < 4; mi++) {
#pragma unroll
        for (int ni = 0; ni < 4; ni++) {
            int trow = t0m + wm * 64 + mi * 16 + g;
            size_t gr0 = (size_t)(bb * TOUT + trow) * N;
            size_t gr1 = gr0 + (size_t)8 * N;
            int gc = n0 + wn * 32 + ni * 8 + tig * 2;
            float* a = acc[mi][ni];
            if (EPI == 0) {
                *(float2*)(outF + gr0 + gc) = make_float2(a[0], a[1]);
                *(float2*)(outF + gr1 + gc) = make_float2(a[2], a[3]);
            } else {
                float b0 = bias[gc], b1 = bias[gc + 1];
                float v0 = gelu_exact(a[0] + b0), v1 = gelu_exact(a[1] + b1);
                float v2 = gelu_exact(a[2] + b0), v3 = gelu_exact(a[3] + b1);
                if (EPI == 1) {
                    *(float2*)(outF + gr0 + gc) = make_float2(v0, v1);
                    *(float2*)(outF + gr1 + gc) = make_float2(v2, v3);
                } else {
                    __nv_bfloat16 h0, l0, h1, l1;
                    fsplit(v0, h0, l0); fsplit(v1, h1, l1);
                    *(__nv_bfloat162*)(outHi + gr0 + gc) = __nv_bfloat162(h0, h1);
                    *(__nv_bfloat162*)(outLo + gr0 + gc) = __nv_bfloat162(l0, l1);
                    fsplit(v2, h0, l0); fsplit(v3, h1, l1);
                    *(__nv_bfloat162*)(outHi + gr1 + gc) = __nv_bfloat162(h0, h1);
                    *(__nv_bfloat162*)(outLo + gr1 + gc) = __nv_bfloat162(l0, l1);
                }
            }
        }
    }
}

// ---------------------------------------------------------------------------
// bias + ChannelNorm + ReLU + bf16-split (and optional fp32 out).
// one block per row (512 channels), 128 threads x 4 channels.
// ---------------------------------------------------------------------------
__global__ __launch_bounds__(128) void k_normsplit(
    const float* __restrict__ raw, const float* __restrict__ bias,
    const float* __restrict__ nw, const float* __restrict__ nb,
    float* __restrict__ outF,
    __nv_bfloat16* __restrict__ oh, __nv_bfloat16* __restrict__ ol) {
    __shared__ float sr[8];
    size_t row = blockIdx.x;
    int t = threadIdx.x, c0 = t * 4;
    float4 v = *(const float4*)(raw + row * CCH + c0);
    float4 b4 = *(const float4*)(bias + c0);
    v.x += b4.x; v.y += b4.y; v.z += b4.z; v.w += b4.w;
    float s1 = v.x + v.y + v.z + v.w;
    float s2 = v.x * v.x + v.y * v.y + v.z * v.z + v.w * v.w;
    int lane = t & 31, w = t >> 5;
#pragma unroll
    for (int o = 16; o > 0; o >>= 1) {
        s1 += __shfl_down_sync(0xffffffffu, s1, o);
        s2 += __shfl_down_sync(0xffffffffu, s2, o);
    }
    if (lane == 0) { sr[w] = s1; sr[w + 4] = s2; }
    __syncthreads();
    float S1 = sr[0] + sr[1] + sr[2] + sr[3];
    float S2 = sr[4] + sr[5] + sr[6] + sr[7];
    float mean = S1 * (1.f / 512.f);
    float var  = (S2 - S1 * S1 * (1.f / 512.f)) * (1.f / 511.f);
    float inv  = rsqrtf(var + 1e-5f);
    float4 g4 = *(const float4*)(nw + c0);
    float4 e4 = *(const float4*)(nb + c0);
    float y0 = fmaxf((v.x - mean) * inv * g4.x + e4.x, 0.f);
    float y1 = fmaxf((v.y - mean) * inv * g4.y + e4.y, 0.f);
    float y2 = fmaxf((v.z - mean) * inv * g4.z + e4.z, 0.f);
    float y3 = fmaxf((v.w - mean) * inv * g4.w + e4.w, 0.f);
    if (outF) *(float4*)(outF + row * CCH + c0) = make_float4(y0, y1, y2, y3);
    __nv_bfloat16 h0, l0, h1, l1;
    fsplit(y0, h0, l0); fsplit(y1, h1, l1);
    *(__nv_bfloat162*)(oh + row * CCH + c0) = __nv_bfloat162(h0, h1);
    *(__nv_bfloat162*)(ol + row * CCH + c0) = __nv_bfloat162(l0, l1);
    fsplit(y2, h0, l0); fsplit(y3, h1, l1);
    *(__nv_bfloat162*)(oh + row * CCH + c0 + 2) = __nv_bfloat162(h0, h1);
    *(__nv_bfloat162*)(ol + row * CCH + c0 + 2) = __nv_bfloat162(l0, l1);
}

// ---------------------------------------------------------------------------
// MLP head: imp = sigmoid(z2 @ w3 + b3) + 1e-5.  One warp per row.
// ---------------------------------------------------------------------------
__global__ __launch_bounds__(256) void k_mlp3(
    const float* __restrict__ z2, const float* __restrict__ w3,
    const float* __restrict__ b3, float* __restrict__ imp) {
    int row = blockIdx.x * 8 + (threadIdx.x >> 5);
    int lane = threadIdx.x & 31;
    const float* zr = z2 + (size_t)row * DMLP;
    float s = 0.f;
    for (int i = lane; i < DMLP; i += 32) s = fmaf(zr[i], w3[i], s);
#pragma unroll
    for (int o = 16; o > 0; o >>= 1) s += __shfl_down_sync(0xffffffffu, s, o);
    if (lane == 0) imp[row] = 1.f / (1.f + expf(-(s + b3[0]))) + 1e-5f;
}

// ---------------------------------------------------------------------------
// Normalize importance + inclusive cumsum. One block per batch.
// ---------------------------------------------------------------------------
__global__ __launch_bounds__(512) void k_scan(const float* __restrict__ imp,
                                              float* __restrict__ cs) {
    __shared__ float sa[512], sb[512];
    int b = blockIdx.x, t = threadIdx.x;
    sa[t] = imp[b * T3 + t];
    __syncthreads();
    float* src = sa;
    float* dst = sb;
    for (int off = 1; off < 512; off <<= 1) {
        float v = src[t] + ((t >= off) ? src[t - off] : 0.f);
        dst[t] = v;
        __syncthreads();
        float* tmp = src; src = dst; dst = tmp;
    }
    float scale = 256.f / src[511];
    cs[b * T3 + t] = src[t] * scale;
}

// ---------------------------------------------------------------------------
// Smartpool warp + final ChannelNorm + ReLU. Output [B][C][TN].
// ---------------------------------------------------------------------------
__global__ __launch_bounds__(512) void k_pool(
    const float* __restrict__ f, const float* __restrict__ cs,
    const float* __restrict__ nw, const float* __restrict__ nb,
    float* __restrict__ out) {
    __shared__ float scs[513];
    __shared__ float sred[64];
    int b = blockIdx.y, n = blockIdx.x, c = threadIdx.x;
    if (c == 0) scs[0] = 0.f;
    scs[c + 1] = cs[b * T3 + c];
    __syncthreads();
    float fn = (float)n;
    bool lastn = (n == TN - 1);
    int lo;
    {
        int a = 0, e = 512;
        while (a < e) { int m = (a + e) >> 1; if (scs[m + 1] > fn) e = m; else a = m + 1; }
        lo = a;
    }
    int hi = 512;
    if (!lastn) {
        int a = 0, e = 512;
        while (a < e) { int m = (a + e) >> 1; if (scs[m] < fn + 1.f) a = m + 1; else e = m; }
        hi = a;
    }
    float acc = 0.f;
    for (int t = lo; t < hi; t++) {
        float x1 = scs[t + 1] - fn, x0 = scs[t] - fn;
        float d1 = lastn ? fmaxf(x1, 0.f) : fminf(fmaxf(x1, 0.f), 1.f);
        float d0 = lastn ? fmaxf(x0, 0.f) : fminf(fmaxf(x0, 0.f), 1.f);
        acc = fmaf(d1 - d0, f[((size_t)(b * T3 + t)) * CCH + c], acc);
    }
    float2 s = block_reduce2(acc, acc * acc, sred);
    float mean = s.x * (1.f / 512.f);
    float var  = (s.y - s.x * s.x * (1.f / 512.f)) * (1.f / 511.f);
    float inv  = rsqrtf(var + 1e-5f);
    float v    = (acc - mean) * inv * nw[c] + nb[c];
    out[((size_t)(b * CCH + c)) * TN + n] = fmaxf(v, 0.f);
}

// ---------------------------------------------------------------------------
// Launch — ordered so the conv1 GEMM is launch index 3 (ncu capture target)
// ---------------------------------------------------------------------------
extern "C" void kernel_launch(void* const* d_in, const int* in_sizes, int n_in,
                              void* d_out, int out_size) {
    (void)in_sizes; (void)n_in; (void)out_size;
    const float* x   = (const float*)d_in[0];
    const float* c0w = (const float*)d_in[1];
    const float* c0b = (const float*)d_in[2];
    const float* c1w = (const float*)d_in[3];
    const float* c1b = (const float*)d_in[4];
    const float* c2w = (const float*)d_in[5];
    const float* c2b = (const float*)d_in[6];
    const float* c3w = (const float*)d_in[7];
    const float* c3b = (const float*)d_in[8];
    const float* w1  = (const float*)d_in[9];
    const float* b1  = (const float*)d_in[10];
    const float* w2  = (const float*)d_in[11];
    const float* b2  = (const float*)d_in[12];
    const float* w3  = (const float*)d_in[13];
    const float* b3  = (const float*)d_in[14];
    const float* n0w = (const float*)d_in[15];
    const float* n0b = (const float*)d_in[16];
    const float* n1w = (const float*)d_in[17];
    const float* n1b = (const float*)d_in[18];
    const float* n2w = (const float*)d_in[19];
    const float* n2b = (const float*)d_in[20];
    const float* n3w = (const float*)d_in[21];
    const float* n3b = (const float*)d_in[22];
    const float* n4w = (const float*)d_in[23];
    const float* n4b = (const float*)d_in[24];
    float* out = (float*)d_out;

    __nv_bfloat16 *p_h0h, *p_h0l, *p_h1h, *p_h1l, *p_h2h, *p_h2l, *p_fh, *p_fl;
    __nv_bfloat16 *p_z1h, *p_z1l;
    __nv_bfloat16 *p_w1h, *p_w1l, *p_w2h, *p_w2l, *p_w3h, *p_w3l;
    __nv_bfloat16 *p_mw1h, *p_mw1l, *p_mw2h, *p_mw2l;
    float *p_f, *p_z2, *p_raw, *p_imp, *p_cs, *p_w0f;
    cudaGetSymbolAddress((void**)&p_h0h, g_h0h);  cudaGetSymbolAddress((void**)&p_h0l, g_h0l);
    cudaGetSymbolAddress((void**)&p_h1h, g_h1h);  cudaGetSymbolAddress((void**)&p_h1l, g_h1l);
    cudaGetSymbolAddress((void**)&p_h2h, g_h2h);  cudaGetSymbolAddress((void**)&p_h2l, g_h2l);
    cudaGetSymbolAddress((void**)&p_fh,  g_fh);   cudaGetSymbolAddress((void**)&p_fl,  g_fl);
    cudaGetSymbolAddress((void**)&p_z1h, g_z1h);  cudaGetSymbolAddress((void**)&p_z1l, g_z1l);
    cudaGetSymbolAddress((void**)&p_w1h, g_w1h);  cudaGetSymbolAddress((void**)&p_w1l, g_w1l);
    cudaGetSymbolAddress((void**)&p_w2h, g_w2h);  cudaGetSymbolAddress((void**)&p_w2l, g_w2l);
    cudaGetSymbolAddress((void**)&p_w3h, g_w3h);  cudaGetSymbolAddress((void**)&p_w3l, g_w3l);
    cudaGetSymbolAddress((void**)&p_mw1h, g_mw1h); cudaGetSymbolAddress((void**)&p_mw1l, g_mw1l);
    cudaGetSymbolAddress((void**)&p_mw2h, g_mw2h); cudaGetSymbolAddress((void**)&p_mw2l, g_mw2l);
    cudaGetSymbolAddress((void**)&p_f,   g_f);
    cudaGetSymbolAddress((void**)&p_z2,  g_z2);
    cudaGetSymbolAddress((void**)&p_raw, g_raw);
    cudaGetSymbolAddress((void**)&p_imp, g_imp);
    cudaGetSymbolAddress((void**)&p_cs,  g_cs);
    cudaGetSymbolAddress((void**)&p_w0f, g_w0f);

    // allow 75,776 B dynamic smem on the GEMM instantiations (host attr, capture-safe)
    cudaFuncSetAttribute(k_tgemm<8, 4, 2, 0>, cudaFuncAttributeMaxDynamicSharedMemorySize, SMEM_TOT);
    cudaFuncSetAttribute(k_tgemm<4, 2, 1, 0>, cudaFuncAttributeMaxDynamicSharedMemorySize, SMEM_TOT);
    cudaFuncSetAttribute(k_tgemm<1, 1, 0, 2>, cudaFuncAttributeMaxDynamicSharedMemorySize, SMEM_TOT);
    cudaFuncSetAttribute(k_tgemm<1, 1, 0, 1>, cudaFuncAttributeMaxDynamicSharedMemorySize, SMEM_TOT);

    // launch 0..2
    k_w0trans<<<(10 * CCH + 255) / 256, 256>>>(c0w, p_w0f);
    k_conv0<<<dim3(T0 / 8, BATCH), 512>>>(x, p_w0f, c0b, n0w, n0b, p_h0h, p_h0l);
    k_wsplit_conv<<<(8 * CCH * CCH) / 256, 256>>>(c1w, p_w1h, p_w1l, CCH, 8, 8 * CCH * CCH);

    // launch 3 -> ncu capture target: conv1 GEMM (M=T1/batch, N=512, K=4096)
    k_tgemm<8, 4, 2, 0><<<dim3(4, T1 / 128, BATCH), 256, SMEM_TOT>>>(
        p_h0h, p_h0l, p_w1h, p_w1l, nullptr, p_raw, nullptr, nullptr,
        T0, T1, CCH, 8 * CCH, CCH);
    k_normsplit<<<BATCH * T1, 128>>>(p_raw, c1b, n1w, n1b, nullptr, p_h1h, p_h1l);

    // conv2
    k_wsplit_conv<<<(4 * CCH * CCH) / 256, 256>>>(c2w, p_w2h, p_w2l, CCH, 4, 4 * CCH * CCH);
    k_tgemm<4, 2, 1, 0><<<dim3(4, T2 / 128, BATCH), 256, SMEM_TOT>>>(
        p_h1h, p_h1l, p_w2h, p_w2l, nullptr, p_raw, nullptr, nullptr,
        T1, T2, CCH, 4 * CCH, CCH);
    k_normsplit<<<BATCH * T2, 128>>>(p_raw, c2b, n2w, n2b, nullptr, p_h2h, p_h2l);

    // conv3
    k_wsplit_conv<<<(4 * CCH * CCH) / 256, 256>>>(c3w, p_w3h, p_w3l, CCH, 4, 4 * CCH * CCH);
    k_tgemm<4, 2, 1, 0><<<dim3(4, T3 / 128, BATCH), 256, SMEM_TOT>>>(
        p_h2h, p_h2l, p_w3h, p_w3l, nullptr, p_raw, nullptr, nullptr,
        T2, T3, CCH, 4 * CCH, CCH);
    k_normsplit<<<BATCH * T3, 128>>>(p_raw, c3b, n3w, n3b, p_f, p_fh, p_fl);

    // importance MLP (tensor)
    k_split<<<(CCH * DMLP) / 256, 256>>>(w1, p_mw1h, p_mw1l, CCH * DMLP);
    k_tgemm<1, 1, 0, 2><<<dim3(DMLP / 128, (BATCH * T3) / 128, 1), 256, SMEM_TOT>>>(
        p_fh, p_fl, p_mw1h, p_mw1l, b1, nullptr, p_z1h, p_z1l,
        BATCH * T3, BATCH * T3, DMLP, CCH, CCH);
    k_split<<<(DMLP * DMLP) / 256, 256>>>(w2, p_mw2h, p_mw2l, DMLP * DMLP);
    k_tgemm<1, 1, 0, 1><<<dim3(DMLP / 128, (BATCH * T3) / 128, 1), 256, SMEM_TOT>>>(
        p_z1h, p_z1l, p_mw2h, p_mw2l, b2, p_z2, nullptr, nullptr,
        BATCH * T3, BATCH * T3, DMLP, DMLP, DMLP);
    k_mlp3<<<(BATCH * T3) / 8, 256>>>(p_z2, w3, b3, p_imp);
    k_scan<<<BATCH, 512>>>(p_imp, p_cs);

    // smartpool warp + final norm
    k_pool<<<dim3(TN, BATCH), 512>>>(p_f, p_cs, n4w, n4b, out);
}

// round 14
// speedup vs baseline: 1.4276x; 1.4276x over previous
#include <cuda_runtime.h>
#include <cuda_bf16.h>
#include <math.h>
#include <stdint.h>

// ---------------------------------------------------------------------------
// Problem constants
// ---------------------------------------------------------------------------
#define BATCH 4
#define LIN   40960
#define CCH   512
#define T0    8192
#define T1    2048
#define T2    1024
#define T3    512
#define TN    256
#define DMLP  2048

// ---------------------------------------------------------------------------
// Scratch (device globals; no allocation allowed)
// ---------------------------------------------------------------------------
__device__ __nv_bfloat16 g_h0h[BATCH * T0 * CCH], g_h0l[BATCH * T0 * CCH];
__device__ __nv_bfloat16 g_h1h[BATCH * T1 * CCH], g_h1l[BATCH * T1 * CCH];
__device__ __nv_bfloat16 g_h2h[BATCH * T2 * CCH], g_h2l[BATCH * T2 * CCH];
__device__ __nv_bfloat16 g_fh [BATCH * T3 * CCH], g_fl [BATCH * T3 * CCH];
__device__ __nv_bfloat16 g_z1h[BATCH * T3 * DMLP], g_z1l[BATCH * T3 * DMLP];
__device__ float g_f  [BATCH * T3 * CCH];
__device__ float g_z2 [BATCH * T3 * DMLP];
__device__ float g_raw[BATCH * T1 * CCH];
__device__ float g_imp[BATCH * T3];
__device__ float g_cs [BATCH * T3];
__device__ __nv_bfloat16 g_w1h[8 * CCH * CCH], g_w1l[8 * CCH * CCH];
__device__ __nv_bfloat16 g_w2h[4 * CCH * CCH], g_w2l[4 * CCH * CCH];
__device__ __nv_bfloat16 g_w3h[4 * CCH * CCH], g_w3l[4 * CCH * CCH];
__device__ __nv_bfloat16 g_mw1h[CCH * DMLP],   g_mw1l[CCH * DMLP];
__device__ __nv_bfloat16 g_mw2h[DMLP * DMLP],  g_mw2l[DMLP * DMLP];
__device__ float g_w0f[10 * CCH];

// ---------------------------------------------------------------------------
// Helpers
// ---------------------------------------------------------------------------
__device__ __forceinline__ int refl(int p, int n) {
    return p < 0 ? -p : (p >= n ? 2 * n - 2 - p : p);
}

__device__ __forceinline__ float gelu_exact(float v) {
    return 0.5f * v * (1.f + erff(v * 0.70710678118654752f));
}

__device__ __forceinline__ void fsplit(float v, __nv_bfloat16& h, __nv_bfloat16& l) {
    h = __float2bfloat16(v);
    l = __float2bfloat16(v - __bfloat162float(h));
}

__device__ __forceinline__ void ldsm_x4(unsigned addr, unsigned* r) {
    asm volatile("ldmatrix.sync.aligned.m8n8.x4.shared.b16 {%0,%1,%2,%3}, [%4];"
                 : "=r"(r[0]), "=r"(r[1]), "=r"(r[2]), "=r"(r[3]) : "r"(addr));
}
__device__ __forceinline__ void ldsm_x2t(unsigned addr, unsigned* r) {
    asm volatile("ldmatrix.sync.aligned.m8n8.x2.trans.shared.b16 {%0,%1}, [%2];"
                 : "=r"(r[0]), "=r"(r[1]) : "r"(addr));
}
__device__ __forceinline__ void mma16816(float* d, const unsigned* a, const unsigned* b) {
    asm volatile(
        "mma.sync.aligned.m16n8k16.row.col.f32.bf16.bf16.f32 "
        "{%0,%1,%2,%3},{%4,%5,%6,%7},{%8,%9},{%0,%1,%2,%3};"
        : "+f"(d[0]), "+f"(d[1]), "+f"(d[2]), "+f"(d[3])
        : "r"(a[0]), "r"(a[1]), "r"(a[2]), "r"(a[3]), "r"(b[0]), "r"(b[1]));
}

// Block-wide (sum, sumsq) reduction. sred >= 64 floats.
__device__ __forceinline__ float2 block_reduce2(float v1, float v2, float* sred) {
    __syncthreads();
    int lane = threadIdx.x & 31, wid = threadIdx.x >> 5;
    int nw = blockDim.x >> 5;
#pragma unroll
    for (int o = 16; o > 0; o >>= 1) {
        v1 += __shfl_down_sync(0xffffffffu, v1, o);
        v2 += __shfl_down_sync(0xffffffffu, v2, o);
    }
    if (lane == 0) { sred[wid] = v1; sred[wid + 32] = v2; }
    __syncthreads();
    if (wid == 0) {
        v1 = (lane < nw) ? sred[lane] : 0.f;
        v2 = (lane < nw) ? sred[lane + 32] : 0.f;
#pragma unroll
        for (int o = 16; o > 0; o >>= 1) {
            v1 += __shfl_down_sync(0xffffffffu, v1, o);
            v2 += __shfl_down_sync(0xffffffffu, v2, o);
        }
        if (lane == 0) { sred[0] = v1; sred[32] = v2; }
    }
    __syncthreads();
    return make_float2(sred[0], sred[32]);
}

// ---------------------------------------------------------------------------
// Weight prep
// ---------------------------------------------------------------------------
// conv weights w[c][ci][tap] -> split bf16 at [(tap*CI+ci)][c]  (K tap-major)
__global__ void k_wsplit_conv(const float* __restrict__ w,
                              __nv_bfloat16* __restrict__ wh,
                              __nv_bfloat16* __restrict__ wl,
                              int CI, int KW, int total) {
    int idx = blockIdx.x * blockDim.x + threadIdx.x;
    if (idx >= total) return;
    int ck = CI * KW;
    int c = idx / ck, rem = idx - c * ck;
    int ci = rem / KW, tap = rem - ci * KW;
    __nv_bfloat16 h, l;
    fsplit(w[idx], h, l);
    int o = (tap * CI + ci) * CCH + c;
    wh[o] = h; wl[o] = l;
}

// plain elementwise split (row-major [K][N] kept)
__global__ void k_split(const float* __restrict__ src,
                        __nv_bfloat16* __restrict__ h,
                        __nv_bfloat16* __restrict__ l, int total) {
    int idx = blockIdx.x * blockDim.x + threadIdx.x;
    if (idx >= total) return;
    __nv_bfloat16 hh, ll;
    fsplit(src[idx], hh, ll);
    h[idx] = hh; l[idx] = ll;
}

// conv0 weight transpose w[c][0][k] -> w0f[k*512+c]
__global__ void k_w0trans(const float* __restrict__ w, float* __restrict__ wt) {
    int idx = blockIdx.x * blockDim.x + threadIdx.x;
    if (idx < 10 * CCH) {
        int c = idx / 10, k = idx - c * 10;
        wt[k * CCH + c] = w[idx];
    }
}

// ---------------------------------------------------------------------------
// conv0 (1->512, k=10, s=5, reflect pad 3) + ChannelNorm + ReLU -> bf16 split
// ---------------------------------------------------------------------------
__global__ __launch_bounds__(512) void k_conv0(
    const float* __restrict__ x, const float* __restrict__ w0t,
    const float* __restrict__ bias, const float* __restrict__ nw,
    const float* __restrict__ nb,
    __nv_bfloat16* __restrict__ oh, __nv_bfloat16* __restrict__ ol) {
    const int TT = 8, KW = 10, S = 5, PAD = 3;
    const int W = S * (TT - 1) + KW;  // 45
    __shared__ float sx[48];
    __shared__ float sred[64];
    int b = blockIdx.y, t0 = blockIdx.x * TT, c = threadIdx.x;
    if (c < W) {
        int p = refl(S * t0 - PAD + c, LIN);
        sx[c] = x[b * LIN + p];
    }
    __syncthreads();
    float acc[TT];
    float bi = bias[c];
#pragma unroll
    for (int tt = 0; tt < TT; tt++) acc[tt] = bi;
#pragma unroll
    for (int k = 0; k < KW; k++) {
        float w = w0t[k * CCH + c];
#pragma unroll
        for (int tt = 0; tt < TT; tt++) acc[tt] = fmaf(w, sx[S * tt + k], acc[tt]);
    }
    float gw = nw[c], gb = nb[c];
    for (int tt = 0; tt < TT; tt++) {
        float2 s = block_reduce2(acc[tt], acc[tt] * acc[tt], sred);
        float mean = s.x * (1.f / 512.f);
        float var  = (s.y - s.x * s.x * (1.f / 512.f)) * (1.f / 511.f);
        float inv  = rsqrtf(var + 1e-5f);
        float v    = fmaxf((acc[tt] - mean) * inv * gw + gb, 0.f);
        __nv_bfloat16 h, l;
        fsplit(v, h, l);
        size_t o = ((size_t)(b * T0 + t0 + tt)) * CCH + c;
        oh[o] = h; ol[o] = l;
    }
}

// ---------------------------------------------------------------------------
// Tensor-core split-bf16 GEMM with implicit im2col A-loader.
//   C[M,N] = A[M,K] * B[K,N];  A row t, k=(tap*512+ci) -> in[b][S*t-PAD+tap][ci]
//   (KW==1 -> plain GEMM)
// 3-pass: AhBh + AhBl + AlBh into fp32 acc.
// BM=128, BN=128, KT=32. *** 512 threads, 16 warps (4x4), warp tile 32x32 ***
// (R13 profile: tensor=51%, occ=12.5%, DRAM=2% -> latency-bound on 2 warps/SMSP;
//  16 warps doubles streams per scheduler.)
// R8 staging (proven fastest): single static smem buffer, 2 syncs, reg prefetch.
// EPI: 0 raw fp32 -> outF;  1 bias+gelu fp32 -> outF;  2 bias+gelu -> split hi/lo
// ---------------------------------------------------------------------------
#define ASTR 40   // A smem row stride in bf16 (80B rows: conflict-free ldmatrix)
#define BSTR 136  // B smem row stride in bf16 (272B rows: conflict-free)

// one uint4 per array per thread (512 threads cover the whole tile)
#define TG_LOAD(KT_IDX)                                                      \
    {                                                                        \
        int kk0 = (KT_IDX) * 32;                                             \
        int tap = (KW == 1) ? 0 : (kk0 >> 9);                                \
        int ci0 = (KW == 1) ? kk0 : (kk0 & 511);                             \
        int tt = t0m + am;                                                   \
        int r = (KW == 1) ? tt : refl(S * tt - PAD + tap, TIN);              \
        size_t offA = (size_t)(bb * TIN + r) * astride + ci0 + akk;          \
        pah = *(const uint4*)(AHi + offA);                                   \
        pal = *(const uint4*)(ALo + offA);                                   \
        size_t offB = (size_t)(kk0 + bk) * N + n0 + bnn;                     \
        pbh = *(const uint4*)(BHi + offB);                                   \
        pbl = *(const uint4*)(BLo + offB);                                   \
    }

template <int KW, int S, int PAD, int EPI>
__global__ __launch_bounds__(512, 1) void k_tgemm(
    const __nv_bfloat16* __restrict__ AHi, const __nv_bfloat16* __restrict__ ALo,
    const __nv_bfloat16* __restrict__ BHi, const __nv_bfloat16* __restrict__ BLo,
    const float* __restrict__ bias, float* __restrict__ outF,
    __nv_bfloat16* __restrict__ outHi, __nv_bfloat16* __restrict__ outLo,
    int TIN, int TOUT, int N, int K, int astride) {
    __shared__ __nv_bfloat16 sAh[128 * ASTR], sAl[128 * ASTR];
    __shared__ __nv_bfloat16 sBh[32 * BSTR], sBl[32 * BSTR];
    const int tid = threadIdx.x;
    const int n0 = blockIdx.x * 128;
    const int t0m = blockIdx.y * 128;
    const int bb = blockIdx.z;

    float acc[2][4][4];
#pragma unroll
    for (int mi = 0; mi < 2; mi++)
#pragma unroll
        for (int ni = 0; ni < 4; ni++)
#pragma unroll
            for (int q = 0; q < 4; q++) acc[mi][ni][q] = 0.f;

    uint4 pah, pal, pbh, pbl;
    const int am = tid >> 2;            // 0..127 (A row)
    const int akk = (tid & 3) * 8;      // A col chunk
    const int bk = tid >> 4;            // 0..31 (B row)
    const int bnn = (tid & 15) * 8;     // B col chunk

    const unsigned baseAh = (unsigned)__cvta_generic_to_shared(sAh);
    const unsigned baseAl = (unsigned)__cvta_generic_to_shared(sAl);
    const unsigned baseBh = (unsigned)__cvta_generic_to_shared(sBh);
    const unsigned baseBl = (unsigned)__cvta_generic_to_shared(sBl);

    const int warp = tid >> 5, lane = tid & 31;
    const int wm = warp >> 2, wn = warp & 3;   // 4x4 warp grid, tile 32x32
    const int lrow = lane & 15, lko = (lane >> 4) * 8;

    const int NKT = K / 32;
    TG_LOAD(0)
    for (int kt = 0; kt < NKT; kt++) {
        __syncthreads();
        *(uint4*)&sAh[am * ASTR + akk] = pah;
        *(uint4*)&sAl[am * ASTR + akk] = pal;
        *(uint4*)&sBh[bk * BSTR + bnn] = pbh;
        *(uint4*)&sBl[bk * BSTR + bnn] = pbl;
        __syncthreads();
        if (kt + 1 < NKT) TG_LOAD(kt + 1)
#pragma unroll
        for (int ks = 0; ks < 2; ks++) {
            unsigned ah[2][4], al[2][4], bh[4][2], bl[4][2];
#pragma unroll
            for (int mi = 0; mi < 2; mi++) {
                int row = wm * 32 + mi * 16 + lrow;
                unsigned offA = (unsigned)((row * ASTR + ks * 16 + lko) * 2);
                ldsm_x4(baseAh + offA, ah[mi]);
                ldsm_x4(baseAl + offA, al[mi]);
            }
#pragma unroll
            for (int ni = 0; ni < 4; ni++) {
                int rb = ks * 16 + lrow;
                unsigned offB = (unsigned)((rb * BSTR + wn * 32 + ni * 8) * 2);
                ldsm_x2t(baseBh + offB, bh[ni]);
                ldsm_x2t(baseBl + offB, bl[ni]);
            }
#pragma unroll
            for (int mi = 0; mi < 2; mi++)
#pragma unroll
                for (int ni = 0; ni < 4; ni++) {
                    mma16816(acc[mi][ni], ah[mi], bh[ni]);
                    mma16816(acc[mi][ni], ah[mi], bl[ni]);
                    mma16816(acc[mi][ni], al[mi], bh[ni]);
                }
        }
    }

    // epilogue
    int g = lane >> 2, tig = lane & 3;
#pragma unroll
    for (int mi = 0; mi < 2; mi++) {
#pragma unroll
        for (int ni = 0; ni < 4; ni++) {
            int trow = t0m + wm * 32 + mi * 16 + g;
            size_t gr0 = (size_t)(bb * TOUT + trow) * N;
            size_t gr1 = gr0 + (size_t)8 * N;
            int gc = n0 + wn * 32 + ni * 8 + tig * 2;
            float* a = acc[mi][ni];
            if (EPI == 0) {
                *(float2*)(outF + gr0 + gc) = make_float2(a[0], a[1]);
                *(float2*)(outF + gr1 + gc) = make_float2(a[2], a[3]);
            } else {
                float b0 = bias[gc], b1 = bias[gc + 1];
                float v0 = gelu_exact(a[0] + b0), v1 = gelu_exact(a[1] + b1);
                float v2 = gelu_exact(a[2] + b0), v3 = gelu_exact(a[3] + b1);
                if (EPI == 1) {
                    *(float2*)(outF + gr0 + gc) = make_float2(v0, v1);
                    *(float2*)(outF + gr1 + gc) = make_float2(v2, v3);
                } else {
                    __nv_bfloat16 h0, l0, h1, l1;
                    fsplit(v0, h0, l0); fsplit(v1, h1, l1);
                    *(__nv_bfloat162*)(outHi + gr0 + gc) = __nv_bfloat162(h0, h1);
                    *(__nv_bfloat162*)(outLo + gr0 + gc) = __nv_bfloat162(l0, l1);
                    fsplit(v2, h0, l0); fsplit(v3, h1, l1);
                    *(__nv_bfloat162*)(outHi + gr1 + gc) = __nv_bfloat162(h0, h1);
                    *(__nv_bfloat162*)(outLo + gr1 + gc) = __nv_bfloat162(l0, l1);
                }
            }
        }
    }
}

// ---------------------------------------------------------------------------
// bias + ChannelNorm + ReLU + bf16-split (and optional fp32 out).
// one block per row (512 channels), 128 threads x 4 channels.
// ---------------------------------------------------------------------------
__global__ __launch_bounds__(128) void k_normsplit(
    const float* __restrict__ raw, const float* __restrict__ bias,
    const float* __restrict__ nw, const float* __restrict__ nb,
    float* __restrict__ outF,
    __nv_bfloat16* __restrict__ oh, __nv_bfloat16* __restrict__ ol) {
    __shared__ float sr[8];
    size_t row = blockIdx.x;
    int t = threadIdx.x, c0 = t * 4;
    float4 v = *(const float4*)(raw + row * CCH + c0);
    float4 b4 = *(const float4*)(bias + c0);
    v.x += b4.x; v.y += b4.y; v.z += b4.z; v.w += b4.w;
    float s1 = v.x + v.y + v.z + v.w;
    float s2 = v.x * v.x + v.y * v.y + v.z * v.z + v.w * v.w;
    int lane = t & 31, w = t >> 5;
#pragma unroll
    for (int o = 16; o > 0; o >>= 1) {
        s1 += __shfl_down_sync(0xffffffffu, s1, o);
        s2 += __shfl_down_sync(0xffffffffu, s2, o);
    }
    if (lane == 0) { sr[w] = s1; sr[w + 4] = s2; }
    __syncthreads();
    float S1 = sr[0] + sr[1] + sr[2] + sr[3];
    float S2 = sr[4] + sr[5] + sr[6] + sr[7];
    float mean = S1 * (1.f / 512.f);
    float var  = (S2 - S1 * S1 * (1.f / 512.f)) * (1.f / 511.f);
    float inv  = rsqrtf(var + 1e-5f);
    float4 g4 = *(const float4*)(nw + c0);
    float4 e4 = *(const float4*)(nb + c0);
    float y0 = fmaxf((v.x - mean) * inv * g4.x + e4.x, 0.f);
    float y1 = fmaxf((v.y - mean) * inv * g4.y + e4.y, 0.f);
    float y2 = fmaxf((v.z - mean) * inv * g4.z + e4.z, 0.f);
    float y3 = fmaxf((v.w - mean) * inv * g4.w + e4.w, 0.f);
    if (outF) *(float4*)(outF + row * CCH + c0) = make_float4(y0, y1, y2, y3);
    __nv_bfloat16 h0, l0, h1, l1;
    fsplit(y0, h0, l0); fsplit(y1, h1, l1);
    *(__nv_bfloat162*)(oh + row * CCH + c0) = __nv_bfloat162(h0, h1);
    *(__nv_bfloat162*)(ol + row * CCH + c0) = __nv_bfloat162(l0, l1);
    fsplit(y2, h0, l0); fsplit(y3, h1, l1);
    *(__nv_bfloat162*)(oh + row * CCH + c0 + 2) = __nv_bfloat162(h0, h1);
    *(__nv_bfloat162*)(ol + row * CCH + c0 + 2) = __nv_bfloat162(l0, l1);
}

// ---------------------------------------------------------------------------
// MLP head: imp = sigmoid(z2 @ w3 + b3) + 1e-5.  One warp per row.
// ---------------------------------------------------------------------------
__global__ __launch_bounds__(256) void k_mlp3(
    const float* __restrict__ z2, const float* __restrict__ w3,
    const float* __restrict__ b3, float* __restrict__ imp) {
    int row = blockIdx.x * 8 + (threadIdx.x >> 5);
    int lane = threadIdx.x & 31;
    const float* zr = z2 + (size_t)row * DMLP;
    float s = 0.f;
    for (int i = lane; i < DMLP; i += 32) s = fmaf(zr[i], w3[i], s);
#pragma unroll
    for (int o = 16; o > 0; o >>= 1) s += __shfl_down_sync(0xffffffffu, s, o);
    if (lane == 0) imp[row] = 1.f / (1.f + expf(-(s + b3[0]))) + 1e-5f;
}

// ---------------------------------------------------------------------------
// Normalize importance + inclusive cumsum. One block per batch.
// ---------------------------------------------------------------------------
__global__ __launch_bounds__(512) void k_scan(const float* __restrict__ imp,
                                              float* __restrict__ cs) {
    __shared__ float sa[512], sb[512];
    int b = blockIdx.x, t = threadIdx.x;
    sa[t] = imp[b * T3 + t];
    __syncthreads();
    float* src = sa;
    float* dst = sb;
    for (int off = 1; off < 512; off <<= 1) {
        float v = src[t] + ((t >= off) ? src[t - off] : 0.f);
        dst[t] = v;
        __syncthreads();
        float* tmp = src; src = dst; dst = tmp;
    }
    float scale = 256.f / src[511];
    cs[b * T3 + t] = src[t] * scale;
}

// ---------------------------------------------------------------------------
// Smartpool warp + final ChannelNorm + ReLU. Output [B][C][TN].
// ---------------------------------------------------------------------------
__global__ __launch_bounds__(512) void k_pool(
    const float* __restrict__ f, const float* __restrict__ cs,
    const float* __restrict__ nw, const float* __restrict__ nb,
    float* __restrict__ out) {
    __shared__ float scs[513];
    __shared__ float sred[64];
    int b = blockIdx.y, n = blockIdx.x, c = threadIdx.x;
    if (c == 0) scs[0] = 0.f;
    scs[c + 1] = cs[b * T3 + c];
    __syncthreads();
    float fn = (float)n;
    bool lastn = (n == TN - 1);
    int lo;
    {
        int a = 0, e = 512;
        while (a < e) { int m = (a + e) >> 1; if (scs[m + 1] > fn) e = m; else a = m + 1; }
        lo = a;
    }
    int hi = 512;
    if (!lastn) {
        int a = 0, e = 512;
        while (a < e) { int m = (a + e) >> 1; if (scs[m] < fn + 1.f) a = m + 1; else e = m; }
        hi = a;
    }
    float acc = 0.f;
    for (int t = lo; t < hi; t++) {
        float x1 = scs[t + 1] - fn, x0 = scs[t] - fn;
        float d1 = lastn ? fmaxf(x1, 0.f) : fminf(fmaxf(x1, 0.f), 1.f);
        float d0 = lastn ? fmaxf(x0, 0.f) : fminf(fmaxf(x0, 0.f), 1.f);
        acc = fmaf(d1 - d0, f[((size_t)(b * T3 + t)) * CCH + c], acc);
    }
    float2 s = block_reduce2(acc, acc * acc, sred);
    float mean = s.x * (1.f / 512.f);
    float var  = (s.y - s.x * s.x * (1.f / 512.f)) * (1.f / 511.f);
    float inv  = rsqrtf(var + 1e-5f);
    float v    = (acc - mean) * inv * nw[c] + nb[c];
    out[((size_t)(b * CCH + c)) * TN + n] = fmaxf(v, 0.f);
}

// ---------------------------------------------------------------------------
// Launch — conv1 GEMM at launch index 3 (ncu capture target)
// ---------------------------------------------------------------------------
extern "C" void kernel_launch(void* const* d_in, const int* in_sizes, int n_in,
                              void* d_out, int out_size) {
    (void)in_sizes; (void)n_in; (void)out_size;
    const float* x   = (const float*)d_in[0];
    const float* c0w = (const float*)d_in[1];
    const float* c0b = (const float*)d_in[2];
    const float* c1w = (const float*)d_in[3];
    const float* c1b = (const float*)d_in[4];
    const float* c2w = (const float*)d_in[5];
    const float* c2b = (const float*)d_in[6];
    const float* c3w = (const float*)d_in[7];
    const float* c3b = (const float*)d_in[8];
    const float* w1  = (const float*)d_in[9];
    const float* b1  = (const float*)d_in[10];
    const float* w2  = (const float*)d_in[11];
    const float* b2  = (const float*)d_in[12];
    const float* w3  = (const float*)d_in[13];
    const float* b3  = (const float*)d_in[14];
    const float* n0w = (const float*)d_in[15];
    const float* n0b = (const float*)d_in[16];
    const float* n1w = (const float*)d_in[17];
    const float* n1b = (const float*)d_in[18];
    const float* n2w = (const float*)d_in[19];
    const float* n2b = (const float*)d_in[20];
    const float* n3w = (const float*)d_in[21];
    const float* n3b = (const float*)d_in[22];
    const float* n4w = (const float*)d_in[23];
    const float* n4b = (const float*)d_in[24];
    float* out = (float*)d_out;

    __nv_bfloat16 *p_h0h, *p_h0l, *p_h1h, *p_h1l, *p_h2h, *p_h2l, *p_fh, *p_fl;
    __nv_bfloat16 *p_z1h, *p_z1l;
    __nv_bfloat16 *p_w1h, *p_w1l, *p_w2h, *p_w2l, *p_w3h, *p_w3l;
    __nv_bfloat16 *p_mw1h, *p_mw1l, *p_mw2h, *p_mw2l;
    float *p_f, *p_z2, *p_raw, *p_imp, *p_cs, *p_w0f;
    cudaGetSymbolAddress((void**)&p_h0h, g_h0h);  cudaGetSymbolAddress((void**)&p_h0l, g_h0l);
    cudaGetSymbolAddress((void**)&p_h1h, g_h1h);  cudaGetSymbolAddress((void**)&p_h1l, g_h1l);
    cudaGetSymbolAddress((void**)&p_h2h, g_h2h);  cudaGetSymbolAddress((void**)&p_h2l, g_h2l);
    cudaGetSymbolAddress((void**)&p_fh,  g_fh);   cudaGetSymbolAddress((void**)&p_fl,  g_fl);
    cudaGetSymbolAddress((void**)&p_z1h, g_z1h);  cudaGetSymbolAddress((void**)&p_z1l, g_z1l);
    cudaGetSymbolAddress((void**)&p_w1h, g_w1h);  cudaGetSymbolAddress((void**)&p_w1l, g_w1l);
    cudaGetSymbolAddress((void**)&p_w2h, g_w2h);  cudaGetSymbolAddress((void**)&p_w2l, g_w2l);
    cudaGetSymbolAddress((void**)&p_w3h, g_w3h);  cudaGetSymbolAddress((void**)&p_w3l, g_w3l);
    cudaGetSymbolAddress((void**)&p_mw1h, g_mw1h); cudaGetSymbolAddress((void**)&p_mw1l, g_mw1l);
    cudaGetSymbolAddress((void**)&p_mw2h, g_mw2h); cudaGetSymbolAddress((void**)&p_mw2l, g_mw2l);
    cudaGetSymbolAddress((void**)&p_f,   g_f);
    cudaGetSymbolAddress((void**)&p_z2,  g_z2);
    cudaGetSymbolAddress((void**)&p_raw, g_raw);
    cudaGetSymbolAddress((void**)&p_imp, g_imp);
    cudaGetSymbolAddress((void**)&p_cs,  g_cs);
    cudaGetSymbolAddress((void**)&p_w0f, g_w0f);

    // launch 0..2
    k_w0trans<<<(10 * CCH + 255) / 256, 256>>>(c0w, p_w0f);
    k_conv0<<<dim3(T0 / 8, BATCH), 512>>>(x, p_w0f, c0b, n0w, n0b, p_h0h, p_h0l);
    k_wsplit_conv<<<(8 * CCH * CCH) / 256, 256>>>(c1w, p_w1h, p_w1l, CCH, 8, 8 * CCH * CCH);

    // launch 3 -> ncu capture target: conv1 GEMM (M=T1/batch, N=512, K=4096)
    k_tgemm<8, 4, 2, 0><<<dim3(4, T1 / 128, BATCH), 512>>>(
        p_h0h, p_h0l, p_w1h, p_w1l, nullptr, p_raw, nullptr, nullptr,
        T0, T1, CCH, 8 * CCH, CCH);
    k_normsplit<<<BATCH * T1, 128>>>(p_raw, c1b, n1w, n1b, nullptr, p_h1h, p_h1l);

    // conv2
    k_wsplit_conv<<<(4 * CCH * CCH) / 256, 256>>>(c2w, p_w2h, p_w2l, CCH, 4, 4 * CCH * CCH);
    k_tgemm<4, 2, 1, 0><<<dim3(4, T2 / 128, BATCH), 512>>>(
        p_h1h, p_h1l, p_w2h, p_w2l, nullptr, p_raw, nullptr, nullptr,
        T1, T2, CCH, 4 * CCH, CCH);
    k_normsplit<<<BATCH * T2, 128>>>(p_raw, c2b, n2w, n2b, nullptr, p_h2h, p_h2l);

    // conv3
    k_wsplit_conv<<<(4 * CCH * CCH) / 256, 256>>>(c3w, p_w3h, p_w3l, CCH, 4, 4 * CCH * CCH);
    k_tgemm<4, 2, 1, 0><<<dim3(4, T3 / 128, BATCH), 512>>>(
        p_h2h, p_h2l, p_w3h, p_w3l, nullptr, p_raw, nullptr, nullptr,
        T2, T3, CCH, 4 * CCH, CCH);
    k_normsplit<<<BATCH * T3, 128>>>(p_raw, c3b, n3w, n3b, p_f, p_fh, p_fl);

    // importance MLP (tensor)
    k_split<<<(CCH * DMLP) / 256, 256>>>(w1, p_mw1h, p_mw1l, CCH * DMLP);
    k_tgemm<1, 1, 0, 2><<<dim3(DMLP / 128, (BATCH * T3) / 128, 1), 512>>>(
        p_fh, p_fl, p_mw1h, p_mw1l, b1, nullptr, p_z1h, p_z1l,
        BATCH * T3, BATCH * T3, DMLP, CCH, CCH);
    k_split<<<(DMLP * DMLP) / 256, 256>>>(w2, p_mw2h, p_mw2l, DMLP * DMLP);
    k_tgemm<1, 1, 0, 1><<<dim3(DMLP / 128, (BATCH * T3) / 128, 1), 512>>>(
        p_z1h, p_z1l, p_mw2h, p_mw2l, b2, p_z2, nullptr, nullptr,
        BATCH * T3, BATCH * T3, DMLP, DMLP, DMLP);
    k_mlp3<<<(BATCH * T3) / 8, 256>>>(p_z2, w3, b3, p_imp);
    k_scan<<<BATCH, 512>>>(p_imp, p_cs);

    // smartpool warp + final norm
    k_pool<<<dim3(TN, BATCH), 512>>>(p_f, p_cs, n4w, n4b, out);
}

// round 15
// speedup vs baseline: 1.5384x; 1.0776x over previous
#include <cuda_runtime.h>
#include <cuda_bf16.h>
#include <math.h>
#include <stdint.h>

// ---------------------------------------------------------------------------
// Problem constants
// ---------------------------------------------------------------------------
#define BATCH 4
#define LIN   40960
#define CCH   512
#define T0    8192
#define T1    2048
#define T2    1024
#define T3    512
#define TN    256
#define DMLP  2048

// ---------------------------------------------------------------------------
// Scratch (device globals; no allocation allowed)
// ---------------------------------------------------------------------------
__device__ __nv_bfloat16 g_h0h[BATCH * T0 * CCH], g_h0l[BATCH * T0 * CCH];
__device__ __nv_bfloat16 g_h1h[BATCH * T1 * CCH], g_h1l[BATCH * T1 * CCH];
__device__ __nv_bfloat16 g_h2h[BATCH * T2 * CCH], g_h2l[BATCH * T2 * CCH];
__device__ __nv_bfloat16 g_fh [BATCH * T3 * CCH], g_fl [BATCH * T3 * CCH];
__device__ __nv_bfloat16 g_z1h[BATCH * T3 * DMLP], g_z1l[BATCH * T3 * DMLP];
__device__ float g_f  [BATCH * T3 * CCH];
__device__ float g_z2 [BATCH * T3 * DMLP];
__device__ float g_raw[BATCH * T1 * CCH];
__device__ float g_imp[BATCH * T3];
__device__ float g_cs [BATCH * T3];
__device__ __nv_bfloat16 g_w1h[8 * CCH * CCH], g_w1l[8 * CCH * CCH];
__device__ __nv_bfloat16 g_w2h[4 * CCH * CCH], g_w2l[4 * CCH * CCH];
__device__ __nv_bfloat16 g_w3h[4 * CCH * CCH], g_w3l[4 * CCH * CCH];
__device__ __nv_bfloat16 g_mw1h[CCH * DMLP],   g_mw1l[CCH * DMLP];
__device__ __nv_bfloat16 g_mw2h[DMLP * DMLP],  g_mw2l[DMLP * DMLP];
__device__ float g_w0f[10 * CCH];

// ---------------------------------------------------------------------------
// Helpers
// ---------------------------------------------------------------------------
__device__ __forceinline__ int refl(int p, int n) {
    return p < 0 ? -p : (p >= n ? 2 * n - 2 - p : p);
}

__device__ __forceinline__ float gelu_exact(float v) {
    return 0.5f * v * (1.f + erff(v * 0.70710678118654752f));
}

__device__ __forceinline__ void fsplit(float v, __nv_bfloat16& h, __nv_bfloat16& l) {
    h = __float2bfloat16(v);
    l = __float2bfloat16(v - __bfloat162float(h));
}

__device__ __forceinline__ void ldsm_x4(unsigned addr, unsigned* r) {
    asm volatile("ldmatrix.sync.aligned.m8n8.x4.shared.b16 {%0,%1,%2,%3}, [%4];"
                 : "=r"(r[0]), "=r"(r[1]), "=r"(r[2]), "=r"(r[3]) : "r"(addr));
}
__device__ __forceinline__ void ldsm_x4t(unsigned addr, unsigned* r) {
    asm volatile("ldmatrix.sync.aligned.m8n8.x4.trans.shared.b16 {%0,%1,%2,%3}, [%4];"
                 : "=r"(r[0]), "=r"(r[1]), "=r"(r[2]), "=r"(r[3]) : "r"(addr));
}
__device__ __forceinline__ void mma16816(float* d, const unsigned* a, const unsigned* b) {
    asm volatile(
        "mma.sync.aligned.m16n8k16.row.col.f32.bf16.bf16.f32 "
        "{%0,%1,%2,%3},{%4,%5,%6,%7},{%8,%9},{%0,%1,%2,%3};"
        : "+f"(d[0]), "+f"(d[1]), "+f"(d[2]), "+f"(d[3])
        : "r"(a[0]), "r"(a[1]), "r"(a[2]), "r"(a[3]), "r"(b[0]), "r"(b[1]));
}

// Block-wide (sum, sumsq) reduction. sred >= 64 floats.
__device__ __forceinline__ float2 block_reduce2(float v1, float v2, float* sred) {
    __syncthreads();
    int lane = threadIdx.x & 31, wid = threadIdx.x >> 5;
    int nw = blockDim.x >> 5;
#pragma unroll
    for (int o = 16; o > 0; o >>= 1) {
        v1 += __shfl_down_sync(0xffffffffu, v1, o);
        v2 += __shfl_down_sync(0xffffffffu, v2, o);
    }
    if (lane == 0) { sred[wid] = v1; sred[wid + 32] = v2; }
    __syncthreads();
    if (wid == 0) {
        v1 = (lane < nw) ? sred[lane] : 0.f;
        v2 = (lane < nw) ? sred[lane + 32] : 0.f;
#pragma unroll
        for (int o = 16; o > 0; o >>= 1) {
            v1 += __shfl_down_sync(0xffffffffu, v1, o);
            v2 += __shfl_down_sync(0xffffffffu, v2, o);
        }
        if (lane == 0) { sred[0] = v1; sred[32] = v2; }
    }
    __syncthreads();
    return make_float2(sred[0], sred[32]);
}

// ---------------------------------------------------------------------------
// Weight prep
// ---------------------------------------------------------------------------
// conv weights w[c][ci][tap] -> split bf16 at [(tap*CI+ci)][c]  (K tap-major)
__global__ void k_wsplit_conv(const float* __restrict__ w,
                              __nv_bfloat16* __restrict__ wh,
                              __nv_bfloat16* __restrict__ wl,
                              int CI, int KW, int total) {
    int idx = blockIdx.x * blockDim.x + threadIdx.x;
    if (idx >= total) return;
    int ck = CI * KW;
    int c = idx / ck, rem = idx - c * ck;
    int ci = rem / KW, tap = rem - ci * KW;
    __nv_bfloat16 h, l;
    fsplit(w[idx], h, l);
    int o = (tap * CI + ci) * CCH + c;
    wh[o] = h; wl[o] = l;
}

// plain elementwise split (row-major [K][N] kept)
__global__ void k_split(const float* __restrict__ src,
                        __nv_bfloat16* __restrict__ h,
                        __nv_bfloat16* __restrict__ l, int total) {
    int idx = blockIdx.x * blockDim.x + threadIdx.x;
    if (idx >= total) return;
    __nv_bfloat16 hh, ll;
    fsplit(src[idx], hh, ll);
    h[idx] = hh; l[idx] = ll;
}

// conv0 weight transpose w[c][0][k] -> w0f[k*512+c]
__global__ void k_w0trans(const float* __restrict__ w, float* __restrict__ wt) {
    int idx = blockIdx.x * blockDim.x + threadIdx.x;
    if (idx < 10 * CCH) {
        int c = idx / 10, k = idx - c * 10;
        wt[k * CCH + c] = w[idx];
    }
}

// ---------------------------------------------------------------------------
// conv0 (1->512, k=10, s=5, reflect pad 3) + ChannelNorm + ReLU -> bf16 split
// ---------------------------------------------------------------------------
__global__ __launch_bounds__(512) void k_conv0(
    const float* __restrict__ x, const float* __restrict__ w0t,
    const float* __restrict__ bias, const float* __restrict__ nw,
    const float* __restrict__ nb,
    __nv_bfloat16* __restrict__ oh, __nv_bfloat16* __restrict__ ol) {
    const int TT = 8, KW = 10, S = 5, PAD = 3;
    const int W = S * (TT - 1) + KW;  // 45
    __shared__ float sx[48];
    __shared__ float sred[64];
    int b = blockIdx.y, t0 = blockIdx.x * TT, c = threadIdx.x;
    if (c < W) {
        int p = refl(S * t0 - PAD + c, LIN);
        sx[c] = x[b * LIN + p];
    }
    __syncthreads();
    float acc[TT];
    float bi = bias[c];
#pragma unroll
    for (int tt = 0; tt < TT; tt++) acc[tt] = bi;
#pragma unroll
    for (int k = 0; k < KW; k++) {
        float w = w0t[k * CCH + c];
#pragma unroll
        for (int tt = 0; tt < TT; tt++) acc[tt] = fmaf(w, sx[S * tt + k], acc[tt]);
    }
    float gw = nw[c], gb = nb[c];
    for (int tt = 0; tt < TT; tt++) {
        float2 s = block_reduce2(acc[tt], acc[tt] * acc[tt], sred);
        float mean = s.x * (1.f / 512.f);
        float var  = (s.y - s.x * s.x * (1.f / 512.f)) * (1.f / 511.f);
        float inv  = rsqrtf(var + 1e-5f);
        float v    = fmaxf((acc[tt] - mean) * inv * gw + gb, 0.f);
        __nv_bfloat16 h, l;
        fsplit(v, h, l);
        size_t o = ((size_t)(b * T0 + t0 + tt)) * CCH + c;
        oh[o] = h; ol[o] = l;
    }
}

// ---------------------------------------------------------------------------
// Tensor-core split-bf16 GEMM with implicit im2col A-loader (R8 staging).
//   C[M,N] = A[M,K] * B[K,N];  A row t, k=(tap*512+ci) -> in[b][S*t-PAD+tap][ci]
// 3-pass: AhBh + AhBl + AlBh into fp32 acc.
// BM=128, BN=128, KT=32. 256 threads, 8 warps (2x4), warp tile 64x32.
// R15 inner loop: ALL fragment loads hoisted (24 ldsm, B via x4.trans) then
// 96 mma with 16 independent acc chains (targets ldsm-latency stalls that
// capped tensor pipe at ~50% in R13/R14 profiles).
// EPI: 0 raw fp32 -> outF;  1 bias+gelu fp32 -> outF;  2 bias+gelu -> split hi/lo
// ---------------------------------------------------------------------------
#define ASTR 40   // A smem row stride in bf16 (80B rows: conflict-free ldmatrix)
#define BSTR 136  // B smem row stride in bf16 (272B rows: conflict-free)

#define TG_LOAD(KT_IDX)                                                      \
    {                                                                        \
        int kk0 = (KT_IDX) * 32;                                             \
        int tap = (KW == 1) ? 0 : (kk0 >> 9);                                \
        int ci0 = (KW == 1) ? kk0 : (kk0 & 511);                             \
        for (int i = 0; i < 2; i++) {                                        \
            int tt = t0m + am[i];                                            \
            int r = (KW == 1) ? tt : refl(S * tt - PAD + tap, TIN);          \
            size_t offA = (size_t)(bb * TIN + r) * astride + ci0 + akk;      \
            pah[i] = *(const uint4*)(AHi + offA);                            \
            pal[i] = *(const uint4*)(ALo + offA);                            \
            size_t offB = (size_t)(kk0 + bk[i]) * N + n0 + bnn;              \
            pbh[i] = *(const uint4*)(BHi + offB);                            \
            pbl[i] = *(const uint4*)(BLo + offB);                            \
        }                                                                    \
    }

template <int KW, int S, int PAD, int EPI>
__global__ __launch_bounds__(256, 1) void k_tgemm(
    const __nv_bfloat16* __restrict__ AHi, const __nv_bfloat16* __restrict__ ALo,
    const __nv_bfloat16* __restrict__ BHi, const __nv_bfloat16* __restrict__ BLo,
    const float* __restrict__ bias, float* __restrict__ outF,
    __nv_bfloat16* __restrict__ outHi, __nv_bfloat16* __restrict__ outLo,
    int TIN, int TOUT, int N, int K, int astride) {
    __shared__ __nv_bfloat16 sAh[128 * ASTR], sAl[128 * ASTR];
    __shared__ __nv_bfloat16 sBh[32 * BSTR], sBl[32 * BSTR];
    const int tid = threadIdx.x;
    const int n0 = blockIdx.x * 128;
    const int t0m = blockIdx.y * 128;
    const int bb = blockIdx.z;

    float acc[4][4][4];
#pragma unroll
    for (int mi = 0; mi < 4; mi++)
#pragma unroll
        for (int ni = 0; ni < 4; ni++)
#pragma unroll
            for (int q = 0; q < 4; q++) acc[mi][ni][q] = 0.f;

    uint4 pah[2], pal[2], pbh[2], pbl[2];
    const int am[2] = { (tid >> 2), (tid >> 2) + 64 };
    const int akk = (tid & 3) * 8;
    const int bk[2] = { (tid >> 4), (tid >> 4) + 16 };
    const int bnn = (tid & 15) * 8;

    const unsigned baseAh = (unsigned)__cvta_generic_to_shared(sAh);
    const unsigned baseAl = (unsigned)__cvta_generic_to_shared(sAl);
    const unsigned baseBh = (unsigned)__cvta_generic_to_shared(sBh);
    const unsigned baseBl = (unsigned)__cvta_generic_to_shared(sBl);

    const int warp = tid >> 5, lane = tid & 31;
    const int wm = warp >> 2, wn = warp & 3;
    const int lrow = lane & 15, lko = (lane >> 4) * 8;
    // x4.trans per-lane B addressing: 4 groups of 8 lanes -> 4 8x8 matrices
    //   groups 0,1: rows k0-7 / k8-15 at col base; groups 2,3: same rows, col base+8
    const int bg = lane >> 3, br = lane & 7;
    const int bt_row = (bg & 1) * 8 + br;     // row within 16-row k-half
    const int bt_col = (bg >> 1) * 8;         // 0 or 8 within 16-col pair

    const int NKT = K / 32;
    TG_LOAD(0)
    for (int kt = 0; kt < NKT; kt++) {
        __syncthreads();
        *(uint4*)&sAh[am[0] * ASTR + akk] = pah[0];
        *(uint4*)&sAh[am[1] * ASTR + akk] = pah[1];
        *(uint4*)&sAl[am[0] * ASTR + akk] = pal[0];
        *(uint4*)&sAl[am[1] * ASTR + akk] = pal[1];
        *(uint4*)&sBh[bk[0] * BSTR + bnn] = pbh[0];
        *(uint4*)&sBh[bk[1] * BSTR + bnn] = pbh[1];
        *(uint4*)&sBl[bk[0] * BSTR + bnn] = pbl[0];
        *(uint4*)&sBl[bk[1] * BSTR + bnn] = pbl[1];
        __syncthreads();
        if (kt + 1 < NKT) TG_LOAD(kt + 1)

        // hoisted fragment loads: 16 A ldsm + 8 B ldsm (x4t), all independent
        unsigned ah[2][4][4], al[2][4][4], bh[2][2][4], bl[2][2][4];
#pragma unroll
        for (int ks = 0; ks < 2; ks++) {
#pragma unroll
            for (int mi = 0; mi < 4; mi++) {
                int row = wm * 64 + mi * 16 + lrow;
                unsigned offA = (unsigned)((row * ASTR + ks * 16 + lko) * 2);
                ldsm_x4(baseAh + offA, ah[ks][mi]);
                ldsm_x4(baseAl + offA, al[ks][mi]);
            }
#pragma unroll
            for (int nip = 0; nip < 2; nip++) {
                int rowB = ks * 16 + bt_row;
                int colB = wn * 32 + nip * 16 + bt_col;
                unsigned offB = (unsigned)((rowB * BSTR + colB) * 2);
                ldsm_x4t(baseBh + offB, bh[ks][nip]);
                ldsm_x4t(baseBl + offB, bl[ks][nip]);
            }
        }
        // 96 mma, 16 independent chains
#pragma unroll
        for (int ks = 0; ks < 2; ks++)
#pragma unroll
            for (int mi = 0; mi < 4; mi++)
#pragma unroll
                for (int ni = 0; ni < 4; ni++) {
                    const unsigned* bhp = &bh[ks][ni >> 1][(ni & 1) * 2];
                    const unsigned* blp = &bl[ks][ni >> 1][(ni & 1) * 2];
                    mma16816(acc[mi][ni], ah[ks][mi], bhp);
                    mma16816(acc[mi][ni], ah[ks][mi], blp);
                    mma16816(acc[mi][ni], al[ks][mi], bhp);
                }
    }

    // epilogue
    int g = lane >> 2, tig = lane & 3;
#pragma unroll
    for (int mi = 0; mi < 4; mi++) {
#pragma unroll
        for (int ni = 0; ni < 4; ni++) {
            int trow = t0m + wm * 64 + mi * 16 + g;
            size_t gr0 = (size_t)(bb * TOUT + trow) * N;
            size_t gr1 = gr0 + (size_t)8 * N;
            int gc = n0 + wn * 32 + ni * 8 + tig * 2;
            float* a = acc[mi][ni];
            if (EPI == 0) {
                *(float2*)(outF + gr0 + gc) = make_float2(a[0], a[1]);
                *(float2*)(outF + gr1 + gc) = make_float2(a[2], a[3]);
            } else {
                float b0 = bias[gc], b1 = bias[gc + 1];
                float v0 = gelu_exact(a[0] + b0), v1 = gelu_exact(a[1] + b1);
                float v2 = gelu_exact(a[2] + b0), v3 = gelu_exact(a[3] + b1);
                if (EPI == 1) {
                    *(float2*)(outF + gr0 + gc) = make_float2(v0, v1);
                    *(float2*)(outF + gr1 + gc) = make_float2(v2, v3);
                } else {
                    __nv_bfloat16 h0, l0, h1, l1;
                    fsplit(v0, h0, l0); fsplit(v1, h1, l1);
                    *(__nv_bfloat162*)(outHi + gr0 + gc) = __nv_bfloat162(h0, h1);
                    *(__nv_bfloat162*)(outLo + gr0 + gc) = __nv_bfloat162(l0, l1);
                    fsplit(v2, h0, l0); fsplit(v3, h1, l1);
                    *(__nv_bfloat162*)(outHi + gr1 + gc) = __nv_bfloat162(h0, h1);
                    *(__nv_bfloat162*)(outLo + gr1 + gc) = __nv_bfloat162(l0, l1);
                }
            }
        }
    }
}

// ---------------------------------------------------------------------------
// bias + ChannelNorm + ReLU + bf16-split (and optional fp32 out).
// one block per row (512 channels), 128 threads x 4 channels.
// ---------------------------------------------------------------------------
__global__ __launch_bounds__(128) void k_normsplit(
    const float* __restrict__ raw, const float* __restrict__ bias,
    const float* __restrict__ nw, const float* __restrict__ nb,
    float* __restrict__ outF,
    __nv_bfloat16* __restrict__ oh, __nv_bfloat16* __restrict__ ol) {
    __shared__ float sr[8];
    size_t row = blockIdx.x;
    int t = threadIdx.x, c0 = t * 4;
    float4 v = *(const float4*)(raw + row * CCH + c0);
    float4 b4 = *(const float4*)(bias + c0);
    v.x += b4.x; v.y += b4.y; v.z += b4.z; v.w += b4.w;
    float s1 = v.x + v.y + v.z + v.w;
    float s2 = v.x * v.x + v.y * v.y + v.z * v.z + v.w * v.w;
    int lane = t & 31, w = t >> 5;
#pragma unroll
    for (int o = 16; o > 0; o >>= 1) {
        s1 += __shfl_down_sync(0xffffffffu, s1, o);
        s2 += __shfl_down_sync(0xffffffffu, s2, o);
    }
    if (lane == 0) { sr[w] = s1; sr[w + 4] = s2; }
    __syncthreads();
    float S1 = sr[0] + sr[1] + sr[2] + sr[3];
    float S2 = sr[4] + sr[5] + sr[6] + sr[7];
    float mean = S1 * (1.f / 512.f);
    float var  = (S2 - S1 * S1 * (1.f / 512.f)) * (1.f / 511.f);
    float inv  = rsqrtf(var + 1e-5f);
    float4 g4 = *(const float4*)(nw + c0);
    float4 e4 = *(const float4*)(nb + c0);
    float y0 = fmaxf((v.x - mean) * inv * g4.x + e4.x, 0.f);
    float y1 = fmaxf((v.y - mean) * inv * g4.y + e4.y, 0.f);
    float y2 = fmaxf((v.z - mean) * inv * g4.z + e4.z, 0.f);
    float y3 = fmaxf((v.w - mean) * inv * g4.w + e4.w, 0.f);
    if (outF) *(float4*)(outF + row * CCH + c0) = make_float4(y0, y1, y2, y3);
    __nv_bfloat16 h0, l0, h1, l1;
    fsplit(y0, h0, l0); fsplit(y1, h1, l1);
    *(__nv_bfloat162*)(oh + row * CCH + c0) = __nv_bfloat162(h0, h1);
    *(__nv_bfloat162*)(ol + row * CCH + c0) = __nv_bfloat162(l0, l1);
    fsplit(y2, h0, l0); fsplit(y3, h1, l1);
    *(__nv_bfloat162*)(oh + row * CCH + c0 + 2) = __nv_bfloat162(h0, h1);
    *(__nv_bfloat162*)(ol + row * CCH + c0 + 2) = __nv_bfloat162(l0, l1);
}

// ---------------------------------------------------------------------------
// MLP head: imp = sigmoid(z2 @ w3 + b3) + 1e-5.  One warp per row.
// ---------------------------------------------------------------------------
__global__ __launch_bounds__(256) void k_mlp3(
    const float* __restrict__ z2, const float* __restrict__ w3,
    const float* __restrict__ b3, float* __restrict__ imp) {
    int row = blockIdx.x * 8 + (threadIdx.x >> 5);
    int lane = threadIdx.x & 31;
    const float* zr = z2 + (size_t)row * DMLP;
    float s = 0.f;
    for (int i = lane; i < DMLP; i += 32) s = fmaf(zr[i], w3[i], s);
#pragma unroll
    for (int o = 16; o > 0; o >>= 1) s += __shfl_down_sync(0xffffffffu, s, o);
    if (lane == 0) imp[row] = 1.f / (1.f + expf(-(s + b3[0]))) + 1e-5f;
}

// ---------------------------------------------------------------------------
// Normalize importance + inclusive cumsum. One block per batch.
// ---------------------------------------------------------------------------
__global__ __launch_bounds__(512) void k_scan(const float* __restrict__ imp,
                                              float* __restrict__ cs) {
    __shared__ float sa[512], sb[512];
    int b = blockIdx.x, t = threadIdx.x;
    sa[t] = imp[b * T3 + t];
    __syncthreads();
    float* src = sa;
    float* dst = sb;
    for (int off = 1; off < 512; off <<= 1) {
        float v = src[t] + ((t >= off) ? src[t - off] : 0.f);
        dst[t] = v;
        __syncthreads();
        float* tmp = src; src = dst; dst = tmp;
    }
    float scale = 256.f / src[511];
    cs[b * T3 + t] = src[t] * scale;
}

// ---------------------------------------------------------------------------
// Smartpool warp + final ChannelNorm + ReLU. Output [B][C][TN].
// ---------------------------------------------------------------------------
__global__ __launch_bounds__(512) void k_pool(
    const float* __restrict__ f, const float* __restrict__ cs,
    const float* __restrict__ nw, const float* __restrict__ nb,
    float* __restrict__ out) {
    __shared__ float scs[513];
    __shared__ float sred[64];
    int b = blockIdx.y, n = blockIdx.x, c = threadIdx.x;
    if (c == 0) scs[0] = 0.f;
    scs[c + 1] = cs[b * T3 + c];
    __syncthreads();
    float fn = (float)n;
    bool lastn = (n == TN - 1);
    int lo;
    {
        int a = 0, e = 512;
        while (a < e) { int m = (a + e) >> 1; if (scs[m + 1] > fn) e = m; else a = m + 1; }
        lo = a;
    }
    int hi = 512;
    if (!lastn) {
        int a = 0, e = 512;
        while (a < e) { int m = (a + e) >> 1; if (scs[m] < fn + 1.f) a = m + 1; else e = m; }
        hi = a;
    }
    float acc = 0.f;
    for (int t = lo; t < hi; t++) {
        float x1 = scs[t + 1] - fn, x0 = scs[t] - fn;
        float d1 = lastn ? fmaxf(x1, 0.f) : fminf(fmaxf(x1, 0.f), 1.f);
        float d0 = lastn ? fmaxf(x0, 0.f) : fminf(fmaxf(x0, 0.f), 1.f);
        acc = fmaf(d1 - d0, f[((size_t)(b * T3 + t)) * CCH + c], acc);
    }
    float2 s = block_reduce2(acc, acc * acc, sred);
    float mean = s.x * (1.f / 512.f);
    float var  = (s.y - s.x * s.x * (1.f / 512.f)) * (1.f / 511.f);
    float inv  = rsqrtf(var + 1e-5f);
    float v    = (acc - mean) * inv * nw[c] + nb[c];
    out[((size_t)(b * CCH + c)) * TN + n] = fmaxf(v, 0.f);
}

// ---------------------------------------------------------------------------
// Launch — conv1 GEMM at launch index 3 (ncu capture target)
// ---------------------------------------------------------------------------
extern "C" void kernel_launch(void* const* d_in, const int* in_sizes, int n_in,
                              void* d_out, int out_size) {
    (void)in_sizes; (void)n_in; (void)out_size;
    const float* x   = (const float*)d_in[0];
    const float* c0w = (const float*)d_in[1];
    const float* c0b = (const float*)d_in[2];
    const float* c1w = (const float*)d_in[3];
    const float* c1b = (const float*)d_in[4];
    const float* c2w = (const float*)d_in[5];
    const float* c2b = (const float*)d_in[6];
    const float* c3w = (const float*)d_in[7];
    const float* c3b = (const float*)d_in[8];
    const float* w1  = (const float*)d_in[9];
    const float* b1  = (const float*)d_in[10];
    const float* w2  = (const float*)d_in[11];
    const float* b2  = (const float*)d_in[12];
    const float* w3  = (const float*)d_in[13];
    const float* b3  = (const float*)d_in[14];
    const float* n0w = (const float*)d_in[15];
    const float* n0b = (const float*)d_in[16];
    const float* n1w = (const float*)d_in[17];
    const float* n1b = (const float*)d_in[18];
    const float* n2w = (const float*)d_in[19];
    const float* n2b = (const float*)d_in[20];
    const float* n3w = (const float*)d_in[21];
    const float* n3b = (const float*)d_in[22];
    const float* n4w = (const float*)d_in[23];
    const float* n4b = (const float*)d_in[24];
    float* out = (float*)d_out;

    __nv_bfloat16 *p_h0h, *p_h0l, *p_h1h, *p_h1l, *p_h2h, *p_h2l, *p_fh, *p_fl;
    __nv_bfloat16 *p_z1h, *p_z1l;
    __nv_bfloat16 *p_w1h, *p_w1l, *p_w2h, *p_w2l, *p_w3h, *p_w3l;
    __nv_bfloat16 *p_mw1h, *p_mw1l, *p_mw2h, *p_mw2l;
    float *p_f, *p_z2, *p_raw, *p_imp, *p_cs, *p_w0f;
    cudaGetSymbolAddress((void**)&p_h0h, g_h0h);  cudaGetSymbolAddress((void**)&p_h0l, g_h0l);
    cudaGetSymbolAddress((void**)&p_h1h, g_h1h);  cudaGetSymbolAddress((void**)&p_h1l, g_h1l);
    cudaGetSymbolAddress((void**)&p_h2h, g_h2h);  cudaGetSymbolAddress((void**)&p_h2l, g_h2l);
    cudaGetSymbolAddress((void**)&p_fh,  g_fh);   cudaGetSymbolAddress((void**)&p_fl,  g_fl);
    cudaGetSymbolAddress((void**)&p_z1h, g_z1h);  cudaGetSymbolAddress((void**)&p_z1l, g_z1l);
    cudaGetSymbolAddress((void**)&p_w1h, g_w1h);  cudaGetSymbolAddress((void**)&p_w1l, g_w1l);
    cudaGetSymbolAddress((void**)&p_w2h, g_w2h);  cudaGetSymbolAddress((void**)&p_w2l, g_w2l);
    cudaGetSymbolAddress((void**)&p_w3h, g_w3h);  cudaGetSymbolAddress((void**)&p_w3l, g_w3l);
    cudaGetSymbolAddress((void**)&p_mw1h, g_mw1h); cudaGetSymbolAddress((void**)&p_mw1l, g_mw1l);
    cudaGetSymbolAddress((void**)&p_mw2h, g_mw2h); cudaGetSymbolAddress((void**)&p_mw2l, g_mw2l);
    cudaGetSymbolAddress((void**)&p_f,   g_f);
    cudaGetSymbolAddress((void**)&p_z2,  g_z2);
    cudaGetSymbolAddress((void**)&p_raw, g_raw);
    cudaGetSymbolAddress((void**)&p_imp, g_imp);
    cudaGetSymbolAddress((void**)&p_cs,  g_cs);
    cudaGetSymbolAddress((void**)&p_w0f, g_w0f);

    // launch 0..2
    k_w0trans<<<(10 * CCH + 255) / 256, 256>>>(c0w, p_w0f);
    k_conv0<<<dim3(T0 / 8, BATCH), 512>>>(x, p_w0f, c0b, n0w, n0b, p_h0h, p_h0l);
    k_wsplit_conv<<<(8 * CCH * CCH) / 256, 256>>>(c1w, p_w1h, p_w1l, CCH, 8, 8 * CCH * CCH);

    // launch 3 -> ncu capture target: conv1 GEMM (per batch M=T1, N=512, K=4096)
    k_tgemm<8, 4, 2, 0><<<dim3(4, T1 / 128, BATCH), 256>>>(
        p_h0h, p_h0l, p_w1h, p_w1l, nullptr, p_raw, nullptr, nullptr,
        T0, T1, CCH, 8 * CCH, CCH);
    k_normsplit<<<BATCH * T1, 128>>>(p_raw, c1b, n1w, n1b, nullptr, p_h1h, p_h1l);

    // conv2
    k_wsplit_conv<<<(4 * CCH * CCH) / 256, 256>>>(c2w, p_w2h, p_w2l, CCH, 4, 4 * CCH * CCH);
    k_tgemm<4, 2, 1, 0><<<dim3(4, T2 / 128, BATCH), 256>>>(
        p_h1h, p_h1l, p_w2h, p_w2l, nullptr, p_raw, nullptr, nullptr,
        T1, T2, CCH, 4 * CCH, CCH);
    k_normsplit<<<BATCH * T2, 128>>>(p_raw, c2b, n2w, n2b, nullptr, p_h2h, p_h2l);

    // conv3
    k_wsplit_conv<<<(4 * CCH * CCH) / 256, 256>>>(c3w, p_w3h, p_w3l, CCH, 4, 4 * CCH * CCH);
    k_tgemm<4, 2, 1, 0><<<dim3(4, T3 / 128, BATCH), 256>>>(
        p_h2h, p_h2l, p_w3h, p_w3l, nullptr, p_raw, nullptr, nullptr,
        T2, T3, CCH, 4 * CCH, CCH);
    k_normsplit<<<BATCH * T3, 128>>>(p_raw, c3b, n3w, n3b, p_f, p_fh, p_fl);

    // importance MLP (tensor)
    k_split<<<(CCH * DMLP) / 256, 256>>>(w1, p_mw1h, p_mw1l, CCH * DMLP);
    k_tgemm<1, 1, 0, 2><<<dim3(DMLP / 128, (BATCH * T3) / 128, 1), 256>>>(
        p_fh, p_fl, p_mw1h, p_mw1l, b1, nullptr, p_z1h, p_z1l,
        BATCH * T3, BATCH * T3, DMLP, CCH, CCH);
    k_split<<<(DMLP * DMLP) / 256, 256>>>(w2, p_mw2h, p_mw2l, DMLP * DMLP);
    k_tgemm<1, 1, 0, 1><<<dim3(DMLP / 128, (BATCH * T3) / 128, 1), 256>>>(
        p_z1h, p_z1l, p_mw2h, p_mw2l, b2, p_z2, nullptr, nullptr,
        BATCH * T3, BATCH * T3, DMLP, DMLP, DMLP);
    k_mlp3<<<(BATCH * T3) / 8, 256>>>(p_z2, w3, b3, p_imp);
    k_scan<<<BATCH, 512>>>(p_imp, p_cs);

    // smartpool warp + final norm
    k_pool<<<dim3(TN, BATCH), 512>>>(p_f, p_cs, n4w, n4b, out);
}

// round 16
// speedup vs baseline: 1.5512x; 1.0083x over previous
#include <cuda_runtime.h>
#include <cuda_bf16.h>
#include <math.h>
#include <stdint.h>

// ---------------------------------------------------------------------------
// Problem constants
// ---------------------------------------------------------------------------
#define BATCH 4
#define LIN   40960
#define CCH   512
#define T0    8192
#define T1    2048
#define T2    1024
#define T3    512
#define TN    256
#define DMLP  2048

// ---------------------------------------------------------------------------
// Scratch (device globals; no allocation allowed)
// ---------------------------------------------------------------------------
__device__ __nv_bfloat16 g_h0h[BATCH * T0 * CCH], g_h0l[BATCH * T0 * CCH];
__device__ __nv_bfloat16 g_h1h[BATCH * T1 * CCH], g_h1l[BATCH * T1 * CCH];
__device__ __nv_bfloat16 g_h2h[BATCH * T2 * CCH], g_h2l[BATCH * T2 * CCH];
__device__ __nv_bfloat16 g_fh [BATCH * T3 * CCH], g_fl [BATCH * T3 * CCH];
__device__ __nv_bfloat16 g_z1h[BATCH * T3 * DMLP], g_z1l[BATCH * T3 * DMLP];
__device__ float g_f  [BATCH * T3 * CCH];
__device__ float g_z2 [BATCH * T3 * DMLP];
__device__ float g_raw[BATCH * T1 * CCH];
__device__ float g_imp[BATCH * T3];
__device__ float g_cs [BATCH * T3];
__device__ __nv_bfloat16 g_w1h[8 * CCH * CCH], g_w1l[8 * CCH * CCH];
__device__ __nv_bfloat16 g_w2h[4 * CCH * CCH], g_w2l[4 * CCH * CCH];
__device__ __nv_bfloat16 g_w3h[4 * CCH * CCH], g_w3l[4 * CCH * CCH];
__device__ __nv_bfloat16 g_mw1h[CCH * DMLP],   g_mw1l[CCH * DMLP];
__device__ __nv_bfloat16 g_mw2h[DMLP * DMLP],  g_mw2l[DMLP * DMLP];
__device__ float g_w0f[10 * CCH];

// ---------------------------------------------------------------------------
// Helpers
// ---------------------------------------------------------------------------
__device__ __forceinline__ int refl(int p, int n) {
    return p < 0 ? -p : (p >= n ? 2 * n - 2 - p : p);
}

__device__ __forceinline__ float gelu_exact(float v) {
    return 0.5f * v * (1.f + erff(v * 0.70710678118654752f));
}

__device__ __forceinline__ void fsplit(float v, __nv_bfloat16& h, __nv_bfloat16& l) {
    h = __float2bfloat16(v);
    l = __float2bfloat16(v - __bfloat162float(h));
}

__device__ __forceinline__ void ldsm_x4(unsigned addr, unsigned* r) {
    asm volatile("ldmatrix.sync.aligned.m8n8.x4.shared.b16 {%0,%1,%2,%3}, [%4];"
                 : "=r"(r[0]), "=r"(r[1]), "=r"(r[2]), "=r"(r[3]) : "r"(addr));
}
__device__ __forceinline__ void ldsm_x4t(unsigned addr, unsigned* r) {
    asm volatile("ldmatrix.sync.aligned.m8n8.x4.trans.shared.b16 {%0,%1,%2,%3}, [%4];"
                 : "=r"(r[0]), "=r"(r[1]), "=r"(r[2]), "=r"(r[3]) : "r"(addr));
}
__device__ __forceinline__ void mma16816(float* d, const unsigned* a, const unsigned* b) {
    asm volatile(
        "mma.sync.aligned.m16n8k16.row.col.f32.bf16.bf16.f32 "
        "{%0,%1,%2,%3},{%4,%5,%6,%7},{%8,%9},{%0,%1,%2,%3};"
        : "+f"(d[0]), "+f"(d[1]), "+f"(d[2]), "+f"(d[3])
        : "r"(a[0]), "r"(a[1]), "r"(a[2]), "r"(a[3]), "r"(b[0]), "r"(b[1]));
}

// Block-wide (sum, sumsq) reduction. sred >= 64 floats.
__device__ __forceinline__ float2 block_reduce2(float v1, float v2, float* sred) {
    __syncthreads();
    int lane = threadIdx.x & 31, wid = threadIdx.x >> 5;
    int nw = blockDim.x >> 5;
#pragma unroll
    for (int o = 16; o > 0; o >>= 1) {
        v1 += __shfl_down_sync(0xffffffffu, v1, o);
        v2 += __shfl_down_sync(0xffffffffu, v2, o);
    }
    if (lane == 0) { sred[wid] = v1; sred[wid + 32] = v2; }
    __syncthreads();
    if (wid == 0) {
        v1 = (lane < nw) ? sred[lane] : 0.f;
        v2 = (lane < nw) ? sred[lane + 32] : 0.f;
#pragma unroll
        for (int o = 16; o > 0; o >>= 1) {
            v1 += __shfl_down_sync(0xffffffffu, v1, o);
            v2 += __shfl_down_sync(0xffffffffu, v2, o);
        }
        if (lane == 0) { sred[0] = v1; sred[32] = v2; }
    }
    __syncthreads();
    return make_float2(sred[0], sred[32]);
}

// ---------------------------------------------------------------------------
// Weight prep
// ---------------------------------------------------------------------------
// conv weights w[c][ci][tap] -> split bf16 at [(tap*CI+ci)][c]  (K tap-major)
__global__ void k_wsplit_conv(const float* __restrict__ w,
                              __nv_bfloat16* __restrict__ wh,
                              __nv_bfloat16* __restrict__ wl,
                              int CI, int KW, int total) {
    int idx = blockIdx.x * blockDim.x + threadIdx.x;
    if (idx >= total) return;
    int ck = CI * KW;
    int c = idx / ck, rem = idx - c * ck;
    int ci = rem / KW, tap = rem - ci * KW;
    __nv_bfloat16 h, l;
    fsplit(w[idx], h, l);
    int o = (tap * CI + ci) * CCH + c;
    wh[o] = h; wl[o] = l;
}

// plain elementwise split (row-major [K][N] kept)
__global__ void k_split(const float* __restrict__ src,
                        __nv_bfloat16* __restrict__ h,
                        __nv_bfloat16* __restrict__ l, int total) {
    int idx = blockIdx.x * blockDim.x + threadIdx.x;
    if (idx >= total) return;
    __nv_bfloat16 hh, ll;
    fsplit(src[idx], hh, ll);
    h[idx] = hh; l[idx] = ll;
}

// conv0 weight transpose w[c][0][k] -> w0f[k*512+c]
__global__ void k_w0trans(const float* __restrict__ w, float* __restrict__ wt) {
    int idx = blockIdx.x * blockDim.x + threadIdx.x;
    if (idx < 10 * CCH) {
        int c = idx / 10, k = idx - c * 10;
        wt[k * CCH + c] = w[idx];
    }
}

// ---------------------------------------------------------------------------
// conv0 (1->512, k=10, s=5, reflect pad 3) + ChannelNorm + ReLU -> bf16 split
// ---------------------------------------------------------------------------
__global__ __launch_bounds__(512) void k_conv0(
    const float* __restrict__ x, const float* __restrict__ w0t,
    const float* __restrict__ bias, const float* __restrict__ nw,
    const float* __restrict__ nb,
    __nv_bfloat16* __restrict__ oh, __nv_bfloat16* __restrict__ ol) {
    const int TT = 8, KW = 10, S = 5, PAD = 3;
    const int W = S * (TT - 1) + KW;  // 45
    __shared__ float sx[48];
    __shared__ float sred[64];
    int b = blockIdx.y, t0 = blockIdx.x * TT, c = threadIdx.x;
    if (c < W) {
        int p = refl(S * t0 - PAD + c, LIN);
        sx[c] = x[b * LIN + p];
    }
    __syncthreads();
    float acc[TT];
    float bi = bias[c];
#pragma unroll
    for (int tt = 0; tt < TT; tt++) acc[tt] = bi;
#pragma unroll
    for (int k = 0; k < KW; k++) {
        float w = w0t[k * CCH + c];
#pragma unroll
        for (int tt = 0; tt < TT; tt++) acc[tt] = fmaf(w, sx[S * tt + k], acc[tt]);
    }
    float gw = nw[c], gb = nb[c];
    for (int tt = 0; tt < TT; tt++) {
        float2 s = block_reduce2(acc[tt], acc[tt] * acc[tt], sred);
        float mean = s.x * (1.f / 512.f);
        float var  = (s.y - s.x * s.x * (1.f / 512.f)) * (1.f / 511.f);
        float inv  = rsqrtf(var + 1e-5f);
        float v    = fmaxf((acc[tt] - mean) * inv * gw + gb, 0.f);
        __nv_bfloat16 h, l;
        fsplit(v, h, l);
        size_t o = ((size_t)(b * T0 + t0 + tt)) * CCH + c;
        oh[o] = h; ol[o] = l;
    }
}

// ---------------------------------------------------------------------------
// Tensor-core split-bf16 GEMM with implicit im2col A-loader (R8 staging).
//   C[M,N] = A[M,K] * B[K,N];  A row t, k=(tap*512+ci) -> in[b][S*t-PAD+tap][ci]
// 3-pass: AhBh + AhBl + AlBh into fp32 acc.
// BM=128, BN=128, KT=32. 256 threads, 8 warps (2x4), warp tile 64x32.
// R16 inner loop: per k-half, hoist 12 ldsm then run the 3 passes OUTERMOST —
// consecutive mmas cycle through all 16 accumulators, so same-acc RAW
// dependencies are 16 apart (R8..R15 had them back-to-back, capping the
// tensor pipe at ~50%).
// EPI: 0 raw fp32 -> outF;  1 bias+gelu fp32 -> outF;  2 bias+gelu -> split hi/lo
// ---------------------------------------------------------------------------
#define ASTR 40   // A smem row stride in bf16 (80B rows: conflict-free ldmatrix)
#define BSTR 136  // B smem row stride in bf16 (272B rows: conflict-free)

#define TG_LOAD(KT_IDX)                                                      \
    {                                                                        \
        int kk0 = (KT_IDX) * 32;                                             \
        int tap = (KW == 1) ? 0 : (kk0 >> 9);                                \
        int ci0 = (KW == 1) ? kk0 : (kk0 & 511);                             \
        for (int i = 0; i < 2; i++) {                                        \
            int tt = t0m + am[i];                                            \
            int r = (KW == 1) ? tt : refl(S * tt - PAD + tap, TIN);          \
            size_t offA = (size_t)(bb * TIN + r) * astride + ci0 + akk;      \
            pah[i] = *(const uint4*)(AHi + offA);                            \
            pal[i] = *(const uint4*)(ALo + offA);                            \
            size_t offB = (size_t)(kk0 + bk[i]) * N + n0 + bnn;              \
            pbh[i] = *(const uint4*)(BHi + offB);                            \
            pbl[i] = *(const uint4*)(BLo + offB);                            \
        }                                                                    \
    }

template <int KW, int S, int PAD, int EPI>
__global__ __launch_bounds__(256, 1) void k_tgemm(
    const __nv_bfloat16* __restrict__ AHi, const __nv_bfloat16* __restrict__ ALo,
    const __nv_bfloat16* __restrict__ BHi, const __nv_bfloat16* __restrict__ BLo,
    const float* __restrict__ bias, float* __restrict__ outF,
    __nv_bfloat16* __restrict__ outHi, __nv_bfloat16* __restrict__ outLo,
    int TIN, int TOUT, int N, int K, int astride) {
    __shared__ __nv_bfloat16 sAh[128 * ASTR], sAl[128 * ASTR];
    __shared__ __nv_bfloat16 sBh[32 * BSTR], sBl[32 * BSTR];
    const int tid = threadIdx.x;
    const int n0 = blockIdx.x * 128;
    const int t0m = blockIdx.y * 128;
    const int bb = blockIdx.z;

    float acc[4][4][4];
#pragma unroll
    for (int mi = 0; mi < 4; mi++)
#pragma unroll
        for (int ni = 0; ni < 4; ni++)
#pragma unroll
            for (int q = 0; q < 4; q++) acc[mi][ni][q] = 0.f;

    uint4 pah[2], pal[2], pbh[2], pbl[2];
    const int am[2] = { (tid >> 2), (tid >> 2) + 64 };
    const int akk = (tid & 3) * 8;
    const int bk[2] = { (tid >> 4), (tid >> 4) + 16 };
    const int bnn = (tid & 15) * 8;

    const unsigned baseAh = (unsigned)__cvta_generic_to_shared(sAh);
    const unsigned baseAl = (unsigned)__cvta_generic_to_shared(sAl);
    const unsigned baseBh = (unsigned)__cvta_generic_to_shared(sBh);
    const unsigned baseBl = (unsigned)__cvta_generic_to_shared(sBl);

    const int warp = tid >> 5, lane = tid & 31;
    const int wm = warp >> 2, wn = warp & 3;
    const int lrow = lane & 15, lko = (lane >> 4) * 8;
    // x4.trans per-lane B addressing (4 groups of 8 lanes -> 4 8x8 matrices)
    const int bg = lane >> 3, br = lane & 7;
    const int bt_row = (bg & 1) * 8 + br;
    const int bt_col = (bg >> 1) * 8;

    const int NKT = K / 32;
    TG_LOAD(0)
    for (int kt = 0; kt < NKT; kt++) {
        __syncthreads();
        *(uint4*)&sAh[am[0] * ASTR + akk] = pah[0];
        *(uint4*)&sAh[am[1] * ASTR + akk] = pah[1];
        *(uint4*)&sAl[am[0] * ASTR + akk] = pal[0];
        *(uint4*)&sAl[am[1] * ASTR + akk] = pal[1];
        *(uint4*)&sBh[bk[0] * BSTR + bnn] = pbh[0];
        *(uint4*)&sBh[bk[1] * BSTR + bnn] = pbh[1];
        *(uint4*)&sBl[bk[0] * BSTR + bnn] = pbl[0];
        *(uint4*)&sBl[bk[1] * BSTR + bnn] = pbl[1];
        __syncthreads();
        if (kt + 1 < NKT) TG_LOAD(kt + 1)

#pragma unroll
        for (int ks = 0; ks < 2; ks++) {
            // hoist this k-half's fragments: 8 A ldsm + 4 B ldsm, independent
            unsigned ah[4][4], al[4][4], bh[2][4], bl[2][4];
#pragma unroll
            for (int mi = 0; mi < 4; mi++) {
                int row = wm * 64 + mi * 16 + lrow;
                unsigned offA = (unsigned)((row * ASTR + ks * 16 + lko) * 2);
                ldsm_x4(baseAh + offA, ah[mi]);
                ldsm_x4(baseAl + offA, al[mi]);
            }
#pragma unroll
            for (int nip = 0; nip < 2; nip++) {
                int rowB = ks * 16 + bt_row;
                int colB = wn * 32 + nip * 16 + bt_col;
                unsigned offB = (unsigned)((rowB * BSTR + colB) * 2);
                ldsm_x4t(baseBh + offB, bh[nip]);
                ldsm_x4t(baseBl + offB, bl[nip]);
            }
            // pass-outermost: consecutive mmas hit 16 distinct accumulators
#pragma unroll
            for (int mi = 0; mi < 4; mi++)
#pragma unroll
                for (int ni = 0; ni < 4; ni++)
                    mma16816(acc[mi][ni], ah[mi], &bh[ni >> 1][(ni & 1) * 2]);
#pragma unroll
            for (int mi = 0; mi < 4; mi++)
#pragma unroll
                for (int ni = 0; ni < 4; ni++)
                    mma16816(acc[mi][ni], ah[mi], &bl[ni >> 1][(ni & 1) * 2]);
#pragma unroll
            for (int mi = 0; mi < 4; mi++)
#pragma unroll
                for (int ni = 0; ni < 4; ni++)
                    mma16816(acc[mi][ni], al[mi], &bh[ni >> 1][(ni & 1) * 2]);
        }
    }

    // epilogue
    int g = lane >> 2, tig = lane & 3;
#pragma unroll
    for (int mi = 0; mi < 4; mi++) {
#pragma unroll
        for (int ni = 0; ni < 4; ni++) {
            int trow = t0m + wm * 64 + mi * 16 + g;
            size_t gr0 = (size_t)(bb * TOUT + trow) * N;
            size_t gr1 = gr0 + (size_t)8 * N;
            int gc = n0 + wn * 32 + ni * 8 + tig * 2;
            float* a = acc[mi][ni];
            if (EPI == 0) {
                *(float2*)(outF + gr0 + gc) = make_float2(a[0], a[1]);
                *(float2*)(outF + gr1 + gc) = make_float2(a[2], a[3]);
            } else {
                float b0 = bias[gc], b1 = bias[gc + 1];
                float v0 = gelu_exact(a[0] + b0), v1 = gelu_exact(a[1] + b1);
                float v2 = gelu_exact(a[2] + b0), v3 = gelu_exact(a[3] + b1);
                if (EPI == 1) {
                    *(float2*)(outF + gr0 + gc) = make_float2(v0, v1);
                    *(float2*)(outF + gr1 + gc) = make_float2(v2, v3);
                } else {
                    __nv_bfloat16 h0, l0, h1, l1;
                    fsplit(v0, h0, l0); fsplit(v1, h1, l1);
                    *(__nv_bfloat162*)(outHi + gr0 + gc) = __nv_bfloat162(h0, h1);
                    *(__nv_bfloat162*)(outLo + gr0 + gc) = __nv_bfloat162(l0, l1);
                    fsplit(v2, h0, l0); fsplit(v3, h1, l1);
                    *(__nv_bfloat162*)(outHi + gr1 + gc) = __nv_bfloat162(h0, h1);
                    *(__nv_bfloat162*)(outLo + gr1 + gc) = __nv_bfloat162(l0, l1);
                }
            }
        }
    }
}

// ---------------------------------------------------------------------------
// bias + ChannelNorm + ReLU + bf16-split (and optional fp32 out).
// one block per row (512 channels), 128 threads x 4 channels.
// ---------------------------------------------------------------------------
__global__ __launch_bounds__(128) void k_normsplit(
    const float* __restrict__ raw, const float* __restrict__ bias,
    const float* __restrict__ nw, const float* __restrict__ nb,
    float* __restrict__ outF,
    __nv_bfloat16* __restrict__ oh, __nv_bfloat16* __restrict__ ol) {
    __shared__ float sr[8];
    size_t row = blockIdx.x;
    int t = threadIdx.x, c0 = t * 4;
    float4 v = *(const float4*)(raw + row * CCH + c0);
    float4 b4 = *(const float4*)(bias + c0);
    v.x += b4.x; v.y += b4.y; v.z += b4.z; v.w += b4.w;
    float s1 = v.x + v.y + v.z + v.w;
    float s2 = v.x * v.x + v.y * v.y + v.z * v.z + v.w * v.w;
    int lane = t & 31, w = t >> 5;
#pragma unroll
    for (int o = 16; o > 0; o >>= 1) {
        s1 += __shfl_down_sync(0xffffffffu, s1, o);
        s2 += __shfl_down_sync(0xffffffffu, s2, o);
    }
    if (lane == 0) { sr[w] = s1; sr[w + 4] = s2; }
    __syncthreads();
    float S1 = sr[0] + sr[1] + sr[2] + sr[3];
    float S2 = sr[4] + sr[5] + sr[6] + sr[7];
    float mean = S1 * (1.f / 512.f);
    float var  = (S2 - S1 * S1 * (1.f / 512.f)) * (1.f / 511.f);
    float inv  = rsqrtf(var + 1e-5f);
    float4 g4 = *(const float4*)(nw + c0);
    float4 e4 = *(const float4*)(nb + c0);
    float y0 = fmaxf((v.x - mean) * inv * g4.x + e4.x, 0.f);
    float y1 = fmaxf((v.y - mean) * inv * g4.y + e4.y, 0.f);
    float y2 = fmaxf((v.z - mean) * inv * g4.z + e4.z, 0.f);
    float y3 = fmaxf((v.w - mean) * inv * g4.w + e4.w, 0.f);
    if (outF) *(float4*)(outF + row * CCH + c0) = make_float4(y0, y1, y2, y3);
    __nv_bfloat16 h0, l0, h1, l1;
    fsplit(y0, h0, l0); fsplit(y1, h1, l1);
    *(__nv_bfloat162*)(oh + row * CCH + c0) = __nv_bfloat162(h0, h1);
    *(__nv_bfloat162*)(ol + row * CCH + c0) = __nv_bfloat162(l0, l1);
    fsplit(y2, h0, l0); fsplit(y3, h1, l1);
    *(__nv_bfloat162*)(oh + row * CCH + c0 + 2) = __nv_bfloat162(h0, h1);
    *(__nv_bfloat162*)(ol + row * CCH + c0 + 2) = __nv_bfloat162(l0, l1);
}

// ---------------------------------------------------------------------------
// MLP head: imp = sigmoid(z2 @ w3 + b3) + 1e-5.  One warp per row.
// ---------------------------------------------------------------------------
__global__ __launch_bounds__(256) void k_mlp3(
    const float* __restrict__ z2, const float* __restrict__ w3,
    const float* __restrict__ b3, float* __restrict__ imp) {
    int row = blockIdx.x * 8 + (threadIdx.x >> 5);
    int lane = threadIdx.x & 31;
    const float* zr = z2 + (size_t)row * DMLP;
    float s = 0.f;
    for (int i = lane; i < DMLP; i += 32) s = fmaf(zr[i], w3[i], s);
#pragma unroll
    for (int o = 16; o > 0; o >>= 1) s += __shfl_down_sync(0xffffffffu, s, o);
    if (lane == 0) imp[row] = 1.f / (1.f + expf(-(s + b3[0]))) + 1e-5f;
}

// ---------------------------------------------------------------------------
// Normalize importance + inclusive cumsum. One block per batch.
// ---------------------------------------------------------------------------
__global__ __launch_bounds__(512) void k_scan(const float* __restrict__ imp,
                                              float* __restrict__ cs) {
    __shared__ float sa[512], sb[512];
    int b = blockIdx.x, t = threadIdx.x;
    sa[t] = imp[b * T3 + t];
    __syncthreads();
    float* src = sa;
    float* dst = sb;
    for (int off = 1; off < 512; off <<= 1) {
        float v = src[t] + ((t >= off) ? src[t - off] : 0.f);
        dst[t] = v;
        __syncthreads();
        float* tmp = src; src = dst; dst = tmp;
    }
    float scale = 256.f / src[511];
    cs[b * T3 + t] = src[t] * scale;
}

// ---------------------------------------------------------------------------
// Smartpool warp + final ChannelNorm + ReLU. Output [B][C][TN].
// ---------------------------------------------------------------------------
__global__ __launch_bounds__(512) void k_pool(
    const float* __restrict__ f, const float* __restrict__ cs,
    const float* __restrict__ nw, const float* __restrict__ nb,
    float* __restrict__ out) {
    __shared__ float scs[513];
    __shared__ float sred[64];
    int b = blockIdx.y, n = blockIdx.x, c = threadIdx.x;
    if (c == 0) scs[0] = 0.f;
    scs[c + 1] = cs[b * T3 + c];
    __syncthreads();
    float fn = (float)n;
    bool lastn = (n == TN - 1);
    int lo;
    {
        int a = 0, e = 512;
        while (a < e) { int m = (a + e) >> 1; if (scs[m + 1] > fn) e = m; else a = m + 1; }
        lo = a;
    }
    int hi = 512;
    if (!lastn) {
        int a = 0, e = 512;
        while (a < e) { int m = (a + e) >> 1; if (scs[m] < fn + 1.f) a = m + 1; else e = m; }
        hi = a;
    }
    float acc = 0.f;
    for (int t = lo; t < hi; t++) {
        float x1 = scs[t + 1] - fn, x0 = scs[t] - fn;
        float d1 = lastn ? fmaxf(x1, 0.f) : fminf(fmaxf(x1, 0.f), 1.f);
        float d0 = lastn ? fmaxf(x0, 0.f) : fminf(fmaxf(x0, 0.f), 1.f);
        acc = fmaf(d1 - d0, f[((size_t)(b * T3 + t)) * CCH + c], acc);
    }
    float2 s = block_reduce2(acc, acc * acc, sred);
    float mean = s.x * (1.f / 512.f);
    float var  = (s.y - s.x * s.x * (1.f / 512.f)) * (1.f / 511.f);
    float inv  = rsqrtf(var + 1e-5f);
    float v    = (acc - mean) * inv * nw[c] + nb[c];
    out[((size_t)(b * CCH + c)) * TN + n] = fmaxf(v, 0.f);
}

// ---------------------------------------------------------------------------
// Launch — conv1 GEMM at launch index 3 (ncu capture target)
// ---------------------------------------------------------------------------
extern "C" void kernel_launch(void* const* d_in, const int* in_sizes, int n_in,
                              void* d_out, int out_size) {
    (void)in_sizes; (void)n_in; (void)out_size;
    const float* x   = (const float*)d_in[0];
    const float* c0w = (const float*)d_in[1];
    const float* c0b = (const float*)d_in[2];
    const float* c1w = (const float*)d_in[3];
    const float* c1b = (const float*)d_in[4];
    const float* c2w = (const float*)d_in[5];
    const float* c2b = (const float*)d_in[6];
    const float* c3w = (const float*)d_in[7];
    const float* c3b = (const float*)d_in[8];
    const float* w1  = (const float*)d_in[9];
    const float* b1  = (const float*)d_in[10];
    const float* w2  = (const float*)d_in[11];
    const float* b2  = (const float*)d_in[12];
    const float* w3  = (const float*)d_in[13];
    const float* b3  = (const float*)d_in[14];
    const float* n0w = (const float*)d_in[15];
    const float* n0b = (const float*)d_in[16];
    const float* n1w = (const float*)d_in[17];
    const float* n1b = (const float*)d_in[18];
    const float* n2w = (const float*)d_in[19];
    const float* n2b = (const float*)d_in[20];
    const float* n3w = (const float*)d_in[21];
    const float* n3b = (const float*)d_in[22];
    const float* n4w = (const float*)d_in[23];
    const float* n4b = (const float*)d_in[24];
    float* out = (float*)d_out;

    __nv_bfloat16 *p_h0h, *p_h0l, *p_h1h, *p_h1l, *p_h2h, *p_h2l, *p_fh, *p_fl;
    __nv_bfloat16 *p_z1h, *p_z1l;
    __nv_bfloat16 *p_w1h, *p_w1l, *p_w2h, *p_w2l, *p_w3h, *p_w3l;
    __nv_bfloat16 *p_mw1h, *p_mw1l, *p_mw2h, *p_mw2l;
    float *p_f, *p_z2, *p_raw, *p_imp, *p_cs, *p_w0f;
    cudaGetSymbolAddress((void**)&p_h0h, g_h0h);  cudaGetSymbolAddress((void**)&p_h0l, g_h0l);
    cudaGetSymbolAddress((void**)&p_h1h, g_h1h);  cudaGetSymbolAddress((void**)&p_h1l, g_h1l);
    cudaGetSymbolAddress((void**)&p_h2h, g_h2h);  cudaGetSymbolAddress((void**)&p_h2l, g_h2l);
    cudaGetSymbolAddress((void**)&p_fh,  g_fh);   cudaGetSymbolAddress((void**)&p_fl,  g_fl);
    cudaGetSymbolAddress((void**)&p_z1h, g_z1h);  cudaGetSymbolAddress((void**)&p_z1l, g_z1l);
    cudaGetSymbolAddress((void**)&p_w1h, g_w1h);  cudaGetSymbolAddress((void**)&p_w1l, g_w1l);
    cudaGetSymbolAddress((void**)&p_w2h, g_w2h);  cudaGetSymbolAddress((void**)&p_w2l, g_w2l);
    cudaGetSymbolAddress((void**)&p_w3h, g_w3h);  cudaGetSymbolAddress((void**)&p_w3l, g_w3l);
    cudaGetSymbolAddress((void**)&p_mw1h, g_mw1h); cudaGetSymbolAddress((void**)&p_mw1l, g_mw1l);
    cudaGetSymbolAddress((void**)&p_mw2h, g_mw2h); cudaGetSymbolAddress((void**)&p_mw2l, g_mw2l);
    cudaGetSymbolAddress((void**)&p_f,   g_f);
    cudaGetSymbolAddress((void**)&p_z2,  g_z2);
    cudaGetSymbolAddress((void**)&p_raw, g_raw);
    cudaGetSymbolAddress((void**)&p_imp, g_imp);
    cudaGetSymbolAddress((void**)&p_cs,  g_cs);
    cudaGetSymbolAddress((void**)&p_w0f, g_w0f);

    // launch 0..2
    k_w0trans<<<(10 * CCH + 255) / 256, 256>>>(c0w, p_w0f);
    k_conv0<<<dim3(T0 / 8, BATCH), 512>>>(x, p_w0f, c0b, n0w, n0b, p_h0h, p_h0l);
    k_wsplit_conv<<<(8 * CCH * CCH) / 256, 256>>>(c1w, p_w1h, p_w1l, CCH, 8, 8 * CCH * CCH);

    // launch 3 -> ncu capture target: conv1 GEMM (per batch M=T1, N=512, K=4096)
    k_tgemm<8, 4, 2, 0><<<dim3(4, T1 / 128, BATCH), 256>>>(
        p_h0h, p_h0l, p_w1h, p_w1l, nullptr, p_raw, nullptr, nullptr,
        T0, T1, CCH, 8 * CCH, CCH);
    k_normsplit<<<BATCH * T1, 128>>>(p_raw, c1b, n1w, n1b, nullptr, p_h1h, p_h1l);

    // conv2
    k_wsplit_conv<<<(4 * CCH * CCH) / 256, 256>>>(c2w, p_w2h, p_w2l, CCH, 4, 4 * CCH * CCH);
    k_tgemm<4, 2, 1, 0><<<dim3(4, T2 / 128, BATCH), 256>>>(
        p_h1h, p_h1l, p_w2h, p_w2l, nullptr, p_raw, nullptr, nullptr,
        T1, T2, CCH, 4 * CCH, CCH);
    k_normsplit<<<BATCH * T2, 128>>>(p_raw, c2b, n2w, n2b, nullptr, p_h2h, p_h2l);

    // conv3
    k_wsplit_conv<<<(4 * CCH * CCH) / 256, 256>>>(c3w, p_w3h, p_w3l, CCH, 4, 4 * CCH * CCH);
    k_tgemm<4, 2, 1, 0><<<dim3(4, T3 / 128, BATCH), 256>>>(
        p_h2h, p_h2l, p_w3h, p_w3l, nullptr, p_raw, nullptr, nullptr,
        T2, T3, CCH, 4 * CCH, CCH);
    k_normsplit<<<BATCH * T3, 128>>>(p_raw, c3b, n3w, n3b, p_f, p_fh, p_fl);

    // importance MLP (tensor)
    k_split<<<(CCH * DMLP) / 256, 256>>>(w1, p_mw1h, p_mw1l, CCH * DMLP);
    k_tgemm<1, 1, 0, 2><<<dim3(DMLP / 128, (BATCH * T3) / 128, 1), 256>>>(
        p_fh, p_fl, p_mw1h, p_mw1l, b1, nullptr, p_z1h, p_z1l,
        BATCH * T3, BATCH * T3, DMLP, CCH, CCH);
    k_split<<<(DMLP * DMLP) / 256, 256>>>(w2, p_mw2h, p_mw2l, DMLP * DMLP);
    k_tgemm<1, 1, 0, 1><<<dim3(DMLP / 128, (BATCH * T3) / 128, 1), 256>>>(
        p_z1h, p_z1l, p_mw2h, p_mw2l, b2, p_z2, nullptr, nullptr,
        BATCH * T3, BATCH * T3, DMLP, DMLP, DMLP);
    k_mlp3<<<(BATCH * T3) / 8, 256>>>(p_z2, w3, b3, p_imp);
    k_scan<<<BATCH, 512>>>(p_imp, p_cs);

    // smartpool warp + final norm
    k_pool<<<dim3(TN, BATCH), 512>>>(p_f, p_cs, n4w, n4b, out);
}

// round 17
// speedup vs baseline: 1.7052x; 1.0993x over previous
#include <cuda_runtime.h>
#include <cuda_bf16.h>
#include <math.h>
#include <stdint.h>

// ---------------------------------------------------------------------------
// Problem constants
// ---------------------------------------------------------------------------
#define BATCH 4
#define LIN   40960
#define CCH   512
#define T0    8192
#define T1    2048
#define T2    1024
#define T3    512
#define TN    256
#define DMLP  2048

// ---------------------------------------------------------------------------
// Scratch (device globals; no allocation allowed)
// ---------------------------------------------------------------------------
__device__ __nv_bfloat16 g_h0h[BATCH * T0 * CCH], g_h0l[BATCH * T0 * CCH];
__device__ __nv_bfloat16 g_h1h[BATCH * T1 * CCH], g_h1l[BATCH * T1 * CCH];
__device__ __nv_bfloat16 g_h2h[BATCH * T2 * CCH], g_h2l[BATCH * T2 * CCH];
__device__ __nv_bfloat16 g_fh [BATCH * T3 * CCH], g_fl [BATCH * T3 * CCH];
__device__ __nv_bfloat16 g_z1h[BATCH * T3 * DMLP], g_z1l[BATCH * T3 * DMLP];
__device__ float g_f  [BATCH * T3 * CCH];
__device__ float g_z2 [BATCH * T3 * DMLP];
__device__ float g_raw[BATCH * T1 * CCH];
__device__ float g_imp[BATCH * T3];
__device__ float g_cs [BATCH * T3];
__device__ __nv_bfloat16 g_w1h[8 * CCH * CCH], g_w1l[8 * CCH * CCH];
__device__ __nv_bfloat16 g_w2h[4 * CCH * CCH], g_w2l[4 * CCH * CCH];
__device__ __nv_bfloat16 g_w3h[4 * CCH * CCH], g_w3l[4 * CCH * CCH];
__device__ __nv_bfloat16 g_mw1h[CCH * DMLP],   g_mw1l[CCH * DMLP];
__device__ __nv_bfloat16 g_mw2h[DMLP * DMLP],  g_mw2l[DMLP * DMLP];
__device__ float g_w0f[10 * CCH];

// ---------------------------------------------------------------------------
// Helpers
// ---------------------------------------------------------------------------
__device__ __forceinline__ int refl(int p, int n) {
    return p < 0 ? -p : (p >= n ? 2 * n - 2 - p : p);
}

__device__ __forceinline__ float gelu_exact(float v) {
    return 0.5f * v * (1.f + erff(v * 0.70710678118654752f));
}

__device__ __forceinline__ void fsplit(float v, __nv_bfloat16& h, __nv_bfloat16& l) {
    h = __float2bfloat16(v);
    l = __float2bfloat16(v - __bfloat162float(h));
}

__device__ __forceinline__ void ldsm_x4(unsigned addr, unsigned* r) {
    asm volatile("ldmatrix.sync.aligned.m8n8.x4.shared.b16 {%0,%1,%2,%3}, [%4];"
                 : "=r"(r[0]), "=r"(r[1]), "=r"(r[2]), "=r"(r[3]) : "r"(addr));
}
__device__ __forceinline__ void ldsm_x4t(unsigned addr, unsigned* r) {
    asm volatile("ldmatrix.sync.aligned.m8n8.x4.trans.shared.b16 {%0,%1,%2,%3}, [%4];"
                 : "=r"(r[0]), "=r"(r[1]), "=r"(r[2]), "=r"(r[3]) : "r"(addr));
}
__device__ __forceinline__ void mma16816(float* d, const unsigned* a, const unsigned* b) {
    asm volatile(
        "mma.sync.aligned.m16n8k16.row.col.f32.bf16.bf16.f32 "
        "{%0,%1,%2,%3},{%4,%5,%6,%7},{%8,%9},{%0,%1,%2,%3};"
        : "+f"(d[0]), "+f"(d[1]), "+f"(d[2]), "+f"(d[3])
        : "r"(a[0]), "r"(a[1]), "r"(a[2]), "r"(a[3]), "r"(b[0]), "r"(b[1]));
}

// Block-wide (sum, sumsq) reduction. sred >= 64 floats.
__device__ __forceinline__ float2 block_reduce2(float v1, float v2, float* sred) {
    __syncthreads();
    int lane = threadIdx.x & 31, wid = threadIdx.x >> 5;
    int nw = blockDim.x >> 5;
#pragma unroll
    for (int o = 16; o > 0; o >>= 1) {
        v1 += __shfl_down_sync(0xffffffffu, v1, o);
        v2 += __shfl_down_sync(0xffffffffu, v2, o);
    }
    if (lane == 0) { sred[wid] = v1; sred[wid + 32] = v2; }
    __syncthreads();
    if (wid == 0) {
        v1 = (lane < nw) ? sred[lane] : 0.f;
        v2 = (lane < nw) ? sred[lane + 32] : 0.f;
#pragma unroll
        for (int o = 16; o > 0; o >>= 1) {
            v1 += __shfl_down_sync(0xffffffffu, v1, o);
            v2 += __shfl_down_sync(0xffffffffu, v2, o);
        }
        if (lane == 0) { sred[0] = v1; sred[32] = v2; }
    }
    __syncthreads();
    return make_float2(sred[0], sred[32]);
}

// ---------------------------------------------------------------------------
// Weight prep
// ---------------------------------------------------------------------------
// conv weights w[c][ci][tap] -> split bf16 at [(tap*CI+ci)][c]  (K tap-major)
__global__ void k_wsplit_conv(const float* __restrict__ w,
                              __nv_bfloat16* __restrict__ wh,
                              __nv_bfloat16* __restrict__ wl,
                              int CI, int KW, int total) {
    int idx = blockIdx.x * blockDim.x + threadIdx.x;
    if (idx >= total) return;
    int ck = CI * KW;
    int c = idx / ck, rem = idx - c * ck;
    int ci = rem / KW, tap = rem - ci * KW;
    __nv_bfloat16 h, l;
    fsplit(w[idx], h, l);
    int o = (tap * CI + ci) * CCH + c;
    wh[o] = h; wl[o] = l;
}

// plain elementwise split (row-major [K][N] kept)
__global__ void k_split(const float* __restrict__ src,
                        __nv_bfloat16* __restrict__ h,
                        __nv_bfloat16* __restrict__ l, int total) {
    int idx = blockIdx.x * blockDim.x + threadIdx.x;
    if (idx >= total) return;
    __nv_bfloat16 hh, ll;
    fsplit(src[idx], hh, ll);
    h[idx] = hh; l[idx] = ll;
}

// conv0 weight transpose w[c][0][k] -> w0f[k*512+c]
__global__ void k_w0trans(const float* __restrict__ w, float* __restrict__ wt) {
    int idx = blockIdx.x * blockDim.x + threadIdx.x;
    if (idx < 10 * CCH) {
        int c = idx / 10, k = idx - c * 10;
        wt[k * CCH + c] = w[idx];
    }
}

// ---------------------------------------------------------------------------
// conv0 (1->512, k=10, s=5, reflect pad 3) + ChannelNorm + ReLU -> bf16 split
// One 128-thread block per (t, b); thread handles 4 channels; single fused
// reduction (normsplit-style) instead of 8 serial block_reduce2 calls.
// ---------------------------------------------------------------------------
__global__ __launch_bounds__(128) void k_conv0(
    const float* __restrict__ x, const float* __restrict__ w0t,
    const float* __restrict__ bias, const float* __restrict__ nw,
    const float* __restrict__ nb,
    __nv_bfloat16* __restrict__ oh, __nv_bfloat16* __restrict__ ol) {
    const int KW = 10, S = 5, PAD = 3;
    __shared__ float sx[KW];
    __shared__ float sr[8];
    int t = blockIdx.x, b = blockIdx.y, j = threadIdx.x, c0 = j * 4;
    if (j < KW) {
        int p = refl(S * t - PAD + j, LIN);
        sx[j] = x[b * LIN + p];
    }
    __syncthreads();
    float4 a = *(const float4*)(bias + c0);
    float av[4] = { a.x, a.y, a.z, a.w };
#pragma unroll
    for (int k = 0; k < KW; k++) {
        float v = sx[k];
        float4 w = *(const float4*)(w0t + k * CCH + c0);
        av[0] = fmaf(w.x, v, av[0]);
        av[1] = fmaf(w.y, v, av[1]);
        av[2] = fmaf(w.z, v, av[2]);
        av[3] = fmaf(w.w, v, av[3]);
    }
    float s1 = av[0] + av[1] + av[2] + av[3];
    float s2 = av[0] * av[0] + av[1] * av[1] + av[2] * av[2] + av[3] * av[3];
    int lane = j & 31, w = j >> 5;
#pragma unroll
    for (int o = 16; o > 0; o >>= 1) {
        s1 += __shfl_down_sync(0xffffffffu, s1, o);
        s2 += __shfl_down_sync(0xffffffffu, s2, o);
    }
    if (lane == 0) { sr[w] = s1; sr[w + 4] = s2; }
    __syncthreads();
    float S1 = sr[0] + sr[1] + sr[2] + sr[3];
    float S2 = sr[4] + sr[5] + sr[6] + sr[7];
    float mean = S1 * (1.f / 512.f);
    float var  = (S2 - S1 * S1 * (1.f / 512.f)) * (1.f / 511.f);
    float inv  = rsqrtf(var + 1e-5f);
    float4 g4 = *(const float4*)(nw + c0);
    float4 e4 = *(const float4*)(nb + c0);
    size_t o = ((size_t)(b * T0 + t)) * CCH + c0;
    float y0 = fmaxf((av[0] - mean) * inv * g4.x + e4.x, 0.f);
    float y1 = fmaxf((av[1] - mean) * inv * g4.y + e4.y, 0.f);
    float y2 = fmaxf((av[2] - mean) * inv * g4.z + e4.z, 0.f);
    float y3 = fmaxf((av[3] - mean) * inv * g4.w + e4.w, 0.f);
    __nv_bfloat16 h0, l0, h1, l1;
    fsplit(y0, h0, l0); fsplit(y1, h1, l1);
    *(__nv_bfloat162*)(oh + o) = __nv_bfloat162(h0, h1);
    *(__nv_bfloat162*)(ol + o) = __nv_bfloat162(l0, l1);
    fsplit(y2, h0, l0); fsplit(y3, h1, l1);
    *(__nv_bfloat162*)(oh + o + 2) = __nv_bfloat162(h0, h1);
    *(__nv_bfloat162*)(ol + o + 2) = __nv_bfloat162(l0, l1);
}

// ---------------------------------------------------------------------------
// Tensor-core split-bf16 GEMM with implicit im2col A-loader.
// R17: KT=64 (half the k-tiles; per-tile fixed overhead ~1500cyc was 2/3 of
// tile time at KT=32). Dynamic smem 71,680B, 1 CTA/SM.
// BM=128, BN=128. 256 threads, 8 warps (2x4), warp tile 64x32.
// 3-pass: AhBh + AhBl + AlBh into fp32 acc; pass-outermost per k16-half.
// EPI: 0 raw fp32; 1 bias+gelu fp32; 2 bias+gelu -> split hi/lo
// ---------------------------------------------------------------------------
#define ASTR 72   // A smem row stride bf16 (144B rows; 144r mod 128 hits 8 phases)
#define BSTR 136  // B smem row stride bf16 (272B rows: conflict-free)
#define OFF_AL 18432u
#define OFF_BH 36864u
#define OFF_BL 54272u
#define SMEM_TOT 71680

#define TG_LOAD(KT_IDX)                                                      \
    {                                                                        \
        int kk0 = (KT_IDX) * 64;                                             \
        int tap = (KW == 1) ? 0 : (kk0 >> 9);                                \
        int ci0 = (KW == 1) ? kk0 : (kk0 & 511);                             \
        for (int i = 0; i < 4; i++) {                                        \
            int ch = tid + i * 256;                                          \
            int arow = ch >> 3, a8 = (ch & 7) * 8;                           \
            int tt = t0m + arow;                                             \
            int r = (KW == 1) ? tt : refl(S * tt - PAD + tap, TIN);          \
            size_t offA = (size_t)(bb * TIN + r) * astride + ci0 + a8;       \
            pah[i] = *(const uint4*)(AHi + offA);                            \
            pal[i] = *(const uint4*)(ALo + offA);                            \
            int brow = ch >> 4, b8 = (ch & 15) * 8;                          \
            size_t offB = (size_t)(kk0 + brow) * N + n0 + b8;                \
            pbh[i] = *(const uint4*)(BHi + offB);                            \
            pbl[i] = *(const uint4*)(BLo + offB);                            \
        }                                                                    \
    }

template <int KW, int S, int PAD, int EPI>
__global__ __launch_bounds__(256) void k_tgemm(
    const __nv_bfloat16* __restrict__ AHi, const __nv_bfloat16* __restrict__ ALo,
    const __nv_bfloat16* __restrict__ BHi, const __nv_bfloat16* __restrict__ BLo,
    const float* __restrict__ bias, float* __restrict__ outF,
    __nv_bfloat16* __restrict__ outHi, __nv_bfloat16* __restrict__ outLo,
    int TIN, int TOUT, int N, int K, int astride) {
    extern __shared__ __align__(16) unsigned char dsm[];
    __nv_bfloat16* sAh = (__nv_bfloat16*)dsm;
    __nv_bfloat16* sAl = (__nv_bfloat16*)(dsm + OFF_AL);
    __nv_bfloat16* sBh = (__nv_bfloat16*)(dsm + OFF_BH);
    __nv_bfloat16* sBl = (__nv_bfloat16*)(dsm + OFF_BL);
    const int tid = threadIdx.x;
    const int n0 = blockIdx.x * 128;
    const int t0m = blockIdx.y * 128;
    const int bb = blockIdx.z;

    float acc[4][4][4];
#pragma unroll
    for (int mi = 0; mi < 4; mi++)
#pragma unroll
        for (int ni = 0; ni < 4; ni++)
#pragma unroll
            for (int q = 0; q < 4; q++) acc[mi][ni][q] = 0.f;

    uint4 pah[4], pal[4], pbh[4], pbl[4];

    const unsigned baseAh = (unsigned)__cvta_generic_to_shared(sAh);
    const unsigned baseAl = (unsigned)__cvta_generic_to_shared(sAl);
    const unsigned baseBh = (unsigned)__cvta_generic_to_shared(sBh);
    const unsigned baseBl = (unsigned)__cvta_generic_to_shared(sBl);

    const int warp = tid >> 5, lane = tid & 31;
    const int wm = warp >> 2, wn = warp & 3;
    const int lrow = lane & 15, lko = (lane >> 4) * 8;
    const int bg = lane >> 3, br = lane & 7;
    const int bt_row = (bg & 1) * 8 + br;
    const int bt_col = (bg >> 1) * 8;

    const int NKT = K / 64;
    TG_LOAD(0)
    for (int kt = 0; kt < NKT; kt++) {
        __syncthreads();
#pragma unroll
        for (int i = 0; i < 4; i++) {
            int ch = tid + i * 256;
            int arow = ch >> 3, a8 = (ch & 7) * 8;
            *(uint4*)&sAh[arow * ASTR + a8] = pah[i];
            *(uint4*)&sAl[arow * ASTR + a8] = pal[i];
            int brow = ch >> 4, b8 = (ch & 15) * 8;
            *(uint4*)&sBh[brow * BSTR + b8] = pbh[i];
            *(uint4*)&sBl[brow * BSTR + b8] = pbl[i];
        }
        __syncthreads();
        if (kt + 1 < NKT) TG_LOAD(kt + 1)

#pragma unroll
        for (int ks = 0; ks < 4; ks++) {
            unsigned ah[4][4], al[4][4], bh[2][4], bl[2][4];
#pragma unroll
            for (int mi = 0; mi < 4; mi++) {
                int row = wm * 64 + mi * 16 + lrow;
                unsigned offA = (unsigned)((row * ASTR + ks * 16 + lko) * 2);
                ldsm_x4(baseAh + offA, ah[mi]);
                ldsm_x4(baseAl + offA, al[mi]);
            }
#pragma unroll
            for (int nip = 0; nip < 2; nip++) {
                int rowB = ks * 16 + bt_row;
                int colB = wn * 32 + nip * 16 + bt_col;
                unsigned offB = (unsigned)((rowB * BSTR + colB) * 2);
                ldsm_x4t(baseBh + offB, bh[nip]);
                ldsm_x4t(baseBl + offB, bl[nip]);
            }
#pragma unroll
            for (int mi = 0; mi < 4; mi++)
#pragma unroll
                for (int ni = 0; ni < 4; ni++)
                    mma16816(acc[mi][ni], ah[mi], &bh[ni >> 1][(ni & 1) * 2]);
#pragma unroll
            for (int mi = 0; mi < 4; mi++)
#pragma unroll
                for (int ni = 0; ni < 4; ni++)
                    mma16816(acc[mi][ni], ah[mi], &bl[ni >> 1][(ni & 1) * 2]);
#pragma unroll
            for (int mi = 0; mi < 4; mi++)
#pragma unroll
                for (int ni = 0; ni < 4; ni++)
                    mma16816(acc[mi][ni], al[mi], &bh[ni >> 1][(ni & 1) * 2]);
        }
    }

    // epilogue
    int g = lane >> 2, tig = lane & 3;
#pragma unroll
    for (int mi = 0; mi < 4; mi++) {
#pragma unroll
        for (int ni = 0; ni < 4; ni++) {
            int trow = t0m + wm * 64 + mi * 16 + g;
            size_t gr0 = (size_t)(bb * TOUT + trow) * N;
            size_t gr1 = gr0 + (size_t)8 * N;
            int gc = n0 + wn * 32 + ni * 8 + tig * 2;
            float* a = acc[mi][ni];
            if (EPI == 0) {
                *(float2*)(outF + gr0 + gc) = make_float2(a[0], a[1]);
                *(float2*)(outF + gr1 + gc) = make_float2(a[2], a[3]);
            } else {
                float b0 = bias[gc], b1 = bias[gc + 1];
                float v0 = gelu_exact(a[0] + b0), v1 = gelu_exact(a[1] + b1);
                float v2 = gelu_exact(a[2] + b0), v3 = gelu_exact(a[3] + b1);
                if (EPI == 1) {
                    *(float2*)(outF + gr0 + gc) = make_float2(v0, v1);
                    *(float2*)(outF + gr1 + gc) = make_float2(v2, v3);
                } else {
                    __nv_bfloat16 h0, l0, h1, l1;
                    fsplit(v0, h0, l0); fsplit(v1, h1, l1);
                    *(__nv_bfloat162*)(outHi + gr0 + gc) = __nv_bfloat162(h0, h1);
                    *(__nv_bfloat162*)(outLo + gr0 + gc) = __nv_bfloat162(l0, l1);
                    fsplit(v2, h0, l0); fsplit(v3, h1, l1);
                    *(__nv_bfloat162*)(outHi + gr1 + gc) = __nv_bfloat162(h0, h1);
                    *(__nv_bfloat162*)(outLo + gr1 + gc) = __nv_bfloat162(l0, l1);
                }
            }
        }
    }
}

// ---------------------------------------------------------------------------
// bias + ChannelNorm + ReLU + bf16-split (and optional fp32 out).
// ---------------------------------------------------------------------------
__global__ __launch_bounds__(128) void k_normsplit(
    const float* __restrict__ raw, const float* __restrict__ bias,
    const float* __restrict__ nw, const float* __restrict__ nb,
    float* __restrict__ outF,
    __nv_bfloat16* __restrict__ oh, __nv_bfloat16* __restrict__ ol) {
    __shared__ float sr[8];
    size_t row = blockIdx.x;
    int t = threadIdx.x, c0 = t * 4;
    float4 v = *(const float4*)(raw + row * CCH + c0);
    float4 b4 = *(const float4*)(bias + c0);
    v.x += b4.x; v.y += b4.y; v.z += b4.z; v.w += b4.w;
    float s1 = v.x + v.y + v.z + v.w;
    float s2 = v.x * v.x + v.y * v.y + v.z * v.z + v.w * v.w;
    int lane = t & 31, w = t >> 5;
#pragma unroll
    for (int o = 16; o > 0; o >>= 1) {
        s1 += __shfl_down_sync(0xffffffffu, s1, o);
        s2 += __shfl_down_sync(0xffffffffu, s2, o);
    }
    if (lane == 0) { sr[w] = s1; sr[w + 4] = s2; }
    __syncthreads();
    float S1 = sr[0] + sr[1] + sr[2] + sr[3];
    float S2 = sr[4] + sr[5] + sr[6] + sr[7];
    float mean = S1 * (1.f / 512.f);
    float var  = (S2 - S1 * S1 * (1.f / 512.f)) * (1.f / 511.f);
    float inv  = rsqrtf(var + 1e-5f);
    float4 g4 = *(const float4*)(nw + c0);
    float4 e4 = *(const float4*)(nb + c0);
    float y0 = fmaxf((v.x - mean) * inv * g4.x + e4.x, 0.f);
    float y1 = fmaxf((v.y - mean) * inv * g4.y + e4.y, 0.f);
    float y2 = fmaxf((v.z - mean) * inv * g4.z + e4.z, 0.f);
    float y3 = fmaxf((v.w - mean) * inv * g4.w + e4.w, 0.f);
    if (outF) *(float4*)(outF + row * CCH + c0) = make_float4(y0, y1, y2, y3);
    __nv_bfloat16 h0, l0, h1, l1;
    fsplit(y0, h0, l0); fsplit(y1, h1, l1);
    *(__nv_bfloat162*)(oh + row * CCH + c0) = __nv_bfloat162(h0, h1);
    *(__nv_bfloat162*)(ol + row * CCH + c0) = __nv_bfloat162(l0, l1);
    fsplit(y2, h0, l0); fsplit(y3, h1, l1);
    *(__nv_bfloat162*)(oh + row * CCH + c0 + 2) = __nv_bfloat162(h0, h1);
    *(__nv_bfloat162*)(ol + row * CCH + c0 + 2) = __nv_bfloat162(l0, l1);
}

// ---------------------------------------------------------------------------
// MLP head: imp = sigmoid(z2 @ w3 + b3) + 1e-5.  One warp per row.
// ---------------------------------------------------------------------------
__global__ __launch_bounds__(256) void k_mlp3(
    const float* __restrict__ z2, const float* __restrict__ w3,
    const float* __restrict__ b3, float* __restrict__ imp) {
    int row = blockIdx.x * 8 + (threadIdx.x >> 5);
    int lane = threadIdx.x & 31;
    const float* zr = z2 + (size_t)row * DMLP;
    float s = 0.f;
    for (int i = lane; i < DMLP; i += 32) s = fmaf(zr[i], w3[i], s);
#pragma unroll
    for (int o = 16; o > 0; o >>= 1) s += __shfl_down_sync(0xffffffffu, s, o);
    if (lane == 0) imp[row] = 1.f / (1.f + expf(-(s + b3[0]))) + 1e-5f;
}

// ---------------------------------------------------------------------------
// Normalize importance + inclusive cumsum. One block per batch.
// ---------------------------------------------------------------------------
__global__ __launch_bounds__(512) void k_scan(const float* __restrict__ imp,
                                              float* __restrict__ cs) {
    __shared__ float sa[512], sb[512];
    int b = blockIdx.x, t = threadIdx.x;
    sa[t] = imp[b * T3 + t];
    __syncthreads();
    float* src = sa;
    float* dst = sb;
    for (int off = 1; off < 512; off <<= 1) {
        float v = src[t] + ((t >= off) ? src[t - off] : 0.f);
        dst[t] = v;
        __syncthreads();
        float* tmp = src; src = dst; dst = tmp;
    }
    float scale = 256.f / src[511];
    cs[b * T3 + t] = src[t] * scale;
}

// ---------------------------------------------------------------------------
// Smartpool warp + final ChannelNorm + ReLU. Output [B][C][TN].
// ---------------------------------------------------------------------------
__global__ __launch_bounds__(512) void k_pool(
    const float* __restrict__ f, const float* __restrict__ cs,
    const float* __restrict__ nw, const float* __restrict__ nb,
    float* __restrict__ out) {
    __shared__ float scs[513];
    __shared__ float sred[64];
    int b = blockIdx.y, n = blockIdx.x, c = threadIdx.x;
    if (c == 0) scs[0] = 0.f;
    scs[c + 1] = cs[b * T3 + c];
    __syncthreads();
    float fn = (float)n;
    bool lastn = (n == TN - 1);
    int lo;
    {
        int a = 0, e = 512;
        while (a < e) { int m = (a + e) >> 1; if (scs[m + 1] > fn) e = m; else a = m + 1; }
        lo = a;
    }
    int hi = 512;
    if (!lastn) {
        int a = 0, e = 512;
        while (a < e) { int m = (a + e) >> 1; if (scs[m] < fn + 1.f) a = m + 1; else e = m; }
        hi = a;
    }
    float acc = 0.f;
    for (int t = lo; t < hi; t++) {
        float x1 = scs[t + 1] - fn, x0 = scs[t] - fn;
        float d1 = lastn ? fmaxf(x1, 0.f) : fminf(fmaxf(x1, 0.f), 1.f);
        float d0 = lastn ? fmaxf(x0, 0.f) : fminf(fmaxf(x0, 0.f), 1.f);
        acc = fmaf(d1 - d0, f[((size_t)(b * T3 + t)) * CCH + c], acc);
    }
    float2 s = block_reduce2(acc, acc * acc, sred);
    float mean = s.x * (1.f / 512.f);
    float var  = (s.y - s.x * s.x * (1.f / 512.f)) * (1.f / 511.f);
    float inv  = rsqrtf(var + 1e-5f);
    float v    = (acc - mean) * inv * nw[c] + nb[c];
    out[((size_t)(b * CCH + c)) * TN + n] = fmaxf(v, 0.f);
}

// ---------------------------------------------------------------------------
// Launch — conv1 GEMM at launch index 3 (ncu capture target)
// ---------------------------------------------------------------------------
extern "C" void kernel_launch(void* const* d_in, const int* in_sizes, int n_in,
                              void* d_out, int out_size) {
    (void)in_sizes; (void)n_in; (void)out_size;
    const float* x   = (const float*)d_in[0];
    const float* c0w = (const float*)d_in[1];
    const float* c0b = (const float*)d_in[2];
    const float* c1w = (const float*)d_in[3];
    const float* c1b = (const float*)d_in[4];
    const float* c2w = (const float*)d_in[5];
    const float* c2b = (const float*)d_in[6];
    const float* c3w = (const float*)d_in[7];
    const float* c3b = (const float*)d_in[8];
    const float* w1  = (const float*)d_in[9];
    const float* b1  = (const float*)d_in[10];
    const float* w2  = (const float*)d_in[11];
    const float* b2  = (const float*)d_in[12];
    const float* w3  = (const float*)d_in[13];
    const float* b3  = (const float*)d_in[14];
    const float* n0w = (const float*)d_in[15];
    const float* n0b = (const float*)d_in[16];
    const float* n1w = (const float*)d_in[17];
    const float* n1b = (const float*)d_in[18];
    const float* n2w = (const float*)d_in[19];
    const float* n2b = (const float*)d_in[20];
    const float* n3w = (const float*)d_in[21];
    const float* n3b = (const float*)d_in[22];
    const float* n4w = (const float*)d_in[23];
    const float* n4b = (const float*)d_in[24];
    float* out = (float*)d_out;

    __nv_bfloat16 *p_h0h, *p_h0l, *p_h1h, *p_h1l, *p_h2h, *p_h2l, *p_fh, *p_fl;
    __nv_bfloat16 *p_z1h, *p_z1l;
    __nv_bfloat16 *p_w1h, *p_w1l, *p_w2h, *p_w2l, *p_w3h, *p_w3l;
    __nv_bfloat16 *p_mw1h, *p_mw1l, *p_mw2h, *p_mw2l;
    float *p_f, *p_z2, *p_raw, *p_imp, *p_cs, *p_w0f;
    cudaGetSymbolAddress((void**)&p_h0h, g_h0h);  cudaGetSymbolAddress((void**)&p_h0l, g_h0l);
    cudaGetSymbolAddress((void**)&p_h1h, g_h1h);  cudaGetSymbolAddress((void**)&p_h1l, g_h1l);
    cudaGetSymbolAddress((void**)&p_h2h, g_h2h);  cudaGetSymbolAddress((void**)&p_h2l, g_h2l);
    cudaGetSymbolAddress((void**)&p_fh,  g_fh);   cudaGetSymbolAddress((void**)&p_fl,  g_fl);
    cudaGetSymbolAddress((void**)&p_z1h, g_z1h);  cudaGetSymbolAddress((void**)&p_z1l, g_z1l);
    cudaGetSymbolAddress((void**)&p_w1h, g_w1h);  cudaGetSymbolAddress((void**)&p_w1l, g_w1l);
    cudaGetSymbolAddress((void**)&p_w2h, g_w2h);  cudaGetSymbolAddress((void**)&p_w2l, g_w2l);
    cudaGetSymbolAddress((void**)&p_w3h, g_w3h);  cudaGetSymbolAddress((void**)&p_w3l, g_w3l);
    cudaGetSymbolAddress((void**)&p_mw1h, g_mw1h); cudaGetSymbolAddress((void**)&p_mw1l, g_mw1l);
    cudaGetSymbolAddress((void**)&p_mw2h, g_mw2h); cudaGetSymbolAddress((void**)&p_mw2l, g_mw2l);
    cudaGetSymbolAddress((void**)&p_f,   g_f);
    cudaGetSymbolAddress((void**)&p_z2,  g_z2);
    cudaGetSymbolAddress((void**)&p_raw, g_raw);
    cudaGetSymbolAddress((void**)&p_imp, g_imp);
    cudaGetSymbolAddress((void**)&p_cs,  g_cs);
    cudaGetSymbolAddress((void**)&p_w0f, g_w0f);

    cudaFuncSetAttribute(k_tgemm<8, 4, 2, 0>, cudaFuncAttributeMaxDynamicSharedMemorySize, SMEM_TOT);
    cudaFuncSetAttribute(k_tgemm<4, 2, 1, 0>, cudaFuncAttributeMaxDynamicSharedMemorySize, SMEM_TOT);
    cudaFuncSetAttribute(k_tgemm<1, 1, 0, 2>, cudaFuncAttributeMaxDynamicSharedMemorySize, SMEM_TOT);
    cudaFuncSetAttribute(k_tgemm<1, 1, 0, 1>, cudaFuncAttributeMaxDynamicSharedMemorySize, SMEM_TOT);

    // launch 0..2
    k_w0trans<<<(10 * CCH + 255) / 256, 256>>>(c0w, p_w0f);
    k_conv0<<<dim3(T0, BATCH), 128>>>(x, p_w0f, c0b, n0w, n0b, p_h0h, p_h0l);
    k_wsplit_conv<<<(8 * CCH * CCH) / 256, 256>>>(c1w, p_w1h, p_w1l, CCH, 8, 8 * CCH * CCH);

    // launch 3 -> ncu capture target: conv1 GEMM (per batch M=T1, N=512, K=4096)
    k_tgemm<8, 4, 2, 0><<<dim3(4, T1 / 128, BATCH), 256, SMEM_TOT>>>(
        p_h0h, p_h0l, p_w1h, p_w1l, nullptr, p_raw, nullptr, nullptr,
        T0, T1, CCH, 8 * CCH, CCH);
    k_normsplit<<<BATCH * T1, 128>>>(p_raw, c1b, n1w, n1b, nullptr, p_h1h, p_h1l);

    // conv2
    k_wsplit_conv<<<(4 * CCH * CCH) / 256, 256>>>(c2w, p_w2h, p_w2l, CCH, 4, 4 * CCH * CCH);
    k_tgemm<4, 2, 1, 0><<<dim3(4, T2 / 128, BATCH), 256, SMEM_TOT>>>(
        p_h1h, p_h1l, p_w2h, p_w2l, nullptr, p_raw, nullptr, nullptr,
        T1, T2, CCH, 4 * CCH, CCH);
    k_normsplit<<<BATCH * T2, 128>>>(p_raw, c2b, n2w, n2b, nullptr, p_h2h, p_h2l);

    // conv3
    k_wsplit_conv<<<(4 * CCH * CCH) / 256, 256>>>(c3w, p_w3h, p_w3l, CCH, 4, 4 * CCH * CCH);
    k_tgemm<4, 2, 1, 0><<<dim3(4, T3 / 128, BATCH), 256, SMEM_TOT>>>(
        p_h2h, p_h2l, p_w3h, p_w3l, nullptr, p_raw, nullptr, nullptr,
        T2, T3, CCH, 4 * CCH, CCH);
    k_normsplit<<<BATCH * T3, 128>>>(p_raw, c3b, n3w, n3b, p_f, p_fh, p_fl);

    // importance MLP (tensor)
    k_split<<<(CCH * DMLP) / 256, 256>>>(w1, p_mw1h, p_mw1l, CCH * DMLP);
    k_tgemm<1, 1, 0, 2><<<dim3(DMLP / 128, (BATCH * T3) / 128, 1), 256, SMEM_TOT>>>(
        p_fh, p_fl, p_mw1h, p_mw1l, b1, nullptr, p_z1h, p_z1l,
        BATCH * T3, BATCH * T3, DMLP, CCH, CCH);
    k_split<<<(DMLP * DMLP) / 256, 256>>>(w2, p_mw2h, p_mw2l, DMLP * DMLP);
    k_tgemm<1, 1, 0, 1><<<dim3(DMLP / 128, (BATCH * T3) / 128, 1), 256, SMEM_TOT>>>(
        p_z1h, p_z1l, p_mw2h, p_mw2l, b2, p_z2, nullptr, nullptr,
        BATCH * T3, BATCH * T3, DMLP, DMLP, DMLP);
    k_mlp3<<<(BATCH * T3) / 8, 256>>>(p_z2, w3, b3, p_imp);
    k_scan<<<BATCH, 512>>>(p_imp, p_cs);

    // smartpool warp + final norm
    k_pool<<<dim3(TN, BATCH), 512>>>(p_f, p_cs, n4w, n4b, out);
}